// round 1
// baseline (speedup 1.0000x reference)
#include <cuda_runtime.h>
#include <math.h>

#define G     128       // B*NV
#define HTOK  192
#define CH    512
#define NHD   8
#define HD    64
#define DFFC  2048
#define NTOK  24576     // G*HTOK
#define NELEM 12582912  // NTOK*CH

// ---------------- scratch (static device globals; allocation-free) ----------
__device__ float g_s1[NELEM];          // normalized src
__device__ float g_qkbuf[NTOK * 1024]; // qk projection
__device__ float g_vbuf[NELEM];        // v projection
__device__ float g_q1[NELEM];          // decayed q, head-major [head][t][d]
__device__ float g_k1[NELEM];          // decayed k
__device__ float g_ot[NELEM];          // token-attn out (head-major flat)
__device__ float g_oh[NELEM];          // hidden-attn out
__device__ float g_hbuf[NTOK * DFFC];  // FF hidden (reused)
__device__ float g_accb[NELEM];        // src2 accumulator
__device__ float g_ps[192 * 512];
__device__ float g_pq[192 * 512];
__device__ float g_scv[512];
__device__ float g_shv[512];

// ---------------- L2 normalize rows of 512 ---------------------------------
__global__ void l2norm_k(const float* __restrict__ X, float* __restrict__ Y) {
    __shared__ float red[4];
    int row = blockIdx.x;
    int tid = threadIdx.x;  // 128
    const float4* xp = reinterpret_cast<const float4*>(X + (size_t)row * CH);
    float4 v = xp[tid];
    float ss = v.x * v.x + v.y * v.y + v.z * v.z + v.w * v.w;
    #pragma unroll
    for (int o = 16; o > 0; o >>= 1) ss += __shfl_xor_sync(0xffffffffu, ss, o);
    if ((tid & 31) == 0) red[tid >> 5] = ss;
    __syncthreads();
    float rn = rsqrtf(red[0] + red[1] + red[2] + red[3]);
    v.x *= rn; v.y *= rn; v.z *= rn; v.w *= rn;
    reinterpret_cast<float4*>(Y + (size_t)row * CH)[tid] = v;
}

// ---------------- generic SGEMM: C = epi(A @ B^T + bias) -------------------
// A [M,K] row-major, B [N,K] row-major (weight [out,in]). M%128==0, N%128==0, K%8==0.
// EPI: 0 = store, 1 = exact GELU, 2 = accumulate into C
template <int EPI>
__global__ void __launch_bounds__(256) sgemm_k(
    const float* __restrict__ A, const float* __restrict__ B,
    const float* __restrict__ bias, float* __restrict__ Cm,
    int M, int N, int K) {
    __shared__ float As[8][128];
    __shared__ float Bs[8][128];
    const int tid = threadIdx.x;
    const int bm = blockIdx.y * 128;
    const int bn = blockIdx.x * 128;
    const int lr = tid >> 1;
    const int lc = (tid & 1) << 2;
    const float* Ap = A + (size_t)(bm + lr) * K + lc;
    const float* Bp = B + (size_t)(bn + lr) * K + lc;
    const int ty = tid >> 4;
    const int tx = tid & 15;
    float acc[8][8];
    #pragma unroll
    for (int i = 0; i < 8; i++)
        #pragma unroll
        for (int j = 0; j < 8; j++) acc[i][j] = 0.f;

    for (int k0 = 0; k0 < K; k0 += 8) {
        float4 av = *reinterpret_cast<const float4*>(Ap + k0);
        float4 bv = *reinterpret_cast<const float4*>(Bp + k0);
        __syncthreads();
        As[lc + 0][lr] = av.x; As[lc + 1][lr] = av.y;
        As[lc + 2][lr] = av.z; As[lc + 3][lr] = av.w;
        Bs[lc + 0][lr] = bv.x; Bs[lc + 1][lr] = bv.y;
        Bs[lc + 2][lr] = bv.z; Bs[lc + 3][lr] = bv.w;
        __syncthreads();
        #pragma unroll
        for (int kk = 0; kk < 8; kk++) {
            float a[8], b[8];
            float4 t0 = *reinterpret_cast<const float4*>(&As[kk][ty << 3]);
            float4 t1 = *reinterpret_cast<const float4*>(&As[kk][(ty << 3) + 4]);
            a[0]=t0.x; a[1]=t0.y; a[2]=t0.z; a[3]=t0.w;
            a[4]=t1.x; a[5]=t1.y; a[6]=t1.z; a[7]=t1.w;
            float4 u0 = *reinterpret_cast<const float4*>(&Bs[kk][tx << 3]);
            float4 u1 = *reinterpret_cast<const float4*>(&Bs[kk][(tx << 3) + 4]);
            b[0]=u0.x; b[1]=u0.y; b[2]=u0.z; b[3]=u0.w;
            b[4]=u1.x; b[5]=u1.y; b[6]=u1.z; b[7]=u1.w;
            #pragma unroll
            for (int i = 0; i < 8; i++)
                #pragma unroll
                for (int j = 0; j < 8; j++)
                    acc[i][j] = fmaf(a[i], b[j], acc[i][j]);
        }
    }
    float bvals[8];
    #pragma unroll
    for (int j = 0; j < 8; j++) bvals[j] = bias[bn + (tx << 3) + j];
    #pragma unroll
    for (int i = 0; i < 8; i++) {
        float* Cp = Cm + (size_t)(bm + (ty << 3) + i) * N + bn + (tx << 3);
        #pragma unroll
        for (int j = 0; j < 8; j++) {
            float v = acc[i][j] + bvals[j];
            if (EPI == 1) v = 0.5f * v * (1.0f + erff(v * 0.70710678118654752f));
            if (EPI == 2) v += Cp[j];
            Cp[j] = v;
        }
    }
}

// ---------------- exponential-decay scan (replaces FFT conv) ---------------
// y[t] = a * r^(H-1-t) * sum_{j<=t} x[j] * r^j,  r = 1 - sigmoid(alpha_d)
__global__ void decay_k(const float* __restrict__ QK, const float* __restrict__ alpha,
                        float* __restrict__ Q1, float* __restrict__ K1) {
    int g = blockIdx.x;      // 0..127
    int which = blockIdx.y;  // 0=q, 1=k
    int ch = threadIdx.x;    // 0..511
    int d = ch & 63;
    int nh = ch >> 6;
    float a = 1.f / (1.f + expf(-alpha[d]));
    float r = 1.f - a;
    float l2r = log2f(r);
    const float* x = QK + (size_t)g * (HTOK * 1024) + which * 512 + ch;
    float* y = (which ? K1 : Q1) + (size_t)g * (NHD * HTOK * HD) +
               (size_t)nh * (HTOK * HD) + d;
    float z = 0.f;
    for (int t = 0; t < HTOK; ++t) {
        z = fmaf(x[(size_t)t * 1024], exp2f((float)t * l2r), z);
        y[(size_t)t * 64] = a * exp2f((float)(HTOK - 1 - t) * l2r) * z;
    }
}

// ---------------- token attention: per head 192x64, online softmax ---------
__global__ void __launch_bounds__(192, 2) tok_attn_k(
    const float* __restrict__ Q1, const float* __restrict__ K1,
    const float* __restrict__ V, float* __restrict__ O) {
    extern __shared__ float sm[];
    float* Ks = sm;           // 12288
    float* Vs = sm + 12288;   // 12288
    int head = blockIdx.x;
    int g = head >> 3, nh = head & 7;
    int tid = threadIdx.x;
    const float4* Ksrc = reinterpret_cast<const float4*>(K1 + (size_t)head * 12288);
    float4* Kd = reinterpret_cast<float4*>(Ks);
    for (int i = tid; i < 3072; i += 192) Kd[i] = Ksrc[i];
    const float* Vbase = V + (size_t)g * HTOK * CH + nh * 64;
    for (int i = tid; i < 12288; i += 192) {
        int t = i >> 6, d = i & 63;
        Vs[i] = Vbase[(size_t)t * CH + d];
    }
    __syncthreads();
    int e = tid;
    float q[64];
    const float4* Qsrc = reinterpret_cast<const float4*>(Q1 + (size_t)head * 12288 + e * 64);
    #pragma unroll
    for (int j = 0; j < 16; j++) {
        float4 v4 = Qsrc[j];
        q[4*j] = v4.x; q[4*j+1] = v4.y; q[4*j+2] = v4.z; q[4*j+3] = v4.w;
    }
    float m = -1e30f, l = 0.f;
    float acc[64];
    #pragma unroll
    for (int j = 0; j < 64; j++) acc[j] = 0.f;
    for (int f = 0; f < HTOK; ++f) {
        const float4* kf = reinterpret_cast<const float4*>(Ks + f * 64);
        float s = 0.f;
        #pragma unroll
        for (int j = 0; j < 16; j++) {
            float4 kv = kf[j];
            s += q[4*j]*kv.x + q[4*j+1]*kv.y + q[4*j+2]*kv.z + q[4*j+3]*kv.w;
        }
        s *= 8.0f;  // * hd**0.5
        float mn = fmaxf(m, s);
        float corr = __expf(m - mn);
        float p = __expf(s - mn);
        l = l * corr + p;
        const float4* vf = reinterpret_cast<const float4*>(Vs + f * 64);
        #pragma unroll
        for (int j = 0; j < 16; j++) {
            float4 vv = vf[j];
            acc[4*j]   = acc[4*j]   * corr + p * vv.x;
            acc[4*j+1] = acc[4*j+1] * corr + p * vv.y;
            acc[4*j+2] = acc[4*j+2] * corr + p * vv.z;
            acc[4*j+3] = acc[4*j+3] * corr + p * vv.w;
        }
        m = mn;
    }
    float inv = 1.0f / l;
    float* Op = O + (size_t)head * 12288 + e * 64;
    #pragma unroll
    for (int d = 0; d < 64; d++) Op[d] = acc[d] * inv;
}

// ---------------- hidden attention: per head 64x64 over 192 ----------------
#define SPAD 65
__global__ void __launch_bounds__(256) hid_attn_k(
    const float* __restrict__ QK, const float* __restrict__ V,
    float* __restrict__ O) {
    extern __shared__ float sm[];
    float* qs = sm;            // 12288  (later reused for V)
    float* ks = sm + 12288;    // 12288
    float* ss = sm + 24576;    // 64*65
    int head = blockIdx.x;
    int g = head >> 3, nh = head & 7;
    int tid = threadIdx.x;
    const float* Qb = QK + (size_t)g * HTOK * 1024 + nh * 64;
    const float* Kb = Qb + 512;
    for (int i = tid; i < 12288; i += 256) {
        int a = i >> 6, e = i & 63;
        qs[i] = Qb[(size_t)a * 1024 + e];
        ks[i] = Kb[(size_t)a * 1024 + e];
    }
    __syncthreads();
    {
        int e = tid & 63;
        int f0 = (tid >> 6) << 4;  // 0,16,32,48
        float sacc[16];
        #pragma unroll
        for (int j = 0; j < 16; j++) sacc[j] = 0.f;
        for (int a = 0; a < HTOK; a++) {
            float qv = qs[a * 64 + e];
            const float* kr = ks + a * 64 + f0;
            #pragma unroll
            for (int j = 0; j < 16; j++) sacc[j] = fmaf(qv, kr[j], sacc[j]);
        }
        #pragma unroll
        for (int j = 0; j < 16; j++) ss[e * SPAD + f0 + j] = sacc[j] * 13.856406460551018f; // sqrt(192)
    }
    __syncthreads();
    if (tid < 64) {
        float* row = ss + tid * SPAD;
        float mx = row[0];
        #pragma unroll 8
        for (int f = 1; f < 64; f++) mx = fmaxf(mx, row[f]);
        float sum = 0.f;
        #pragma unroll 8
        for (int f = 0; f < 64; f++) { float p = __expf(row[f] - mx); row[f] = p; sum += p; }
        float inv = 1.0f / sum;
        #pragma unroll 8
        for (int f = 0; f < 64; f++) row[f] *= inv;
    }
    __syncthreads();
    const float* Vb = V + (size_t)g * HTOK * CH + nh * 64;
    for (int i = tid; i < 12288; i += 256) {
        int a = i >> 6, d = i & 63;
        qs[i] = Vb[(size_t)a * CH + d];
    }
    __syncthreads();
    float* Op = O + (size_t)head * 12288;
    for (int o = tid; o < 12288; o += 256) {
        int a = o >> 6, e = o & 63;
        const float* ar = ss + e * SPAD;
        const float* vr = qs + a * 64;
        float s = 0.f;
        #pragma unroll
        for (int f = 0; f < 64; f++) s = fmaf(ar[f], vr[f], s);
        Op[o] = s;
    }
}

// ---------------- BatchNorm (train-mode batch stats, per 512-channel) ------
__global__ void bn_partial_k(const float* __restrict__ X, const float* __restrict__ X2,
                             float* __restrict__ psum, float* __restrict__ psq) {
    int chunk = blockIdx.x;   // 192 chunks of 128 rows
    int ch = threadIdx.x;     // 512
    const float* p = X + (size_t)chunk * 128 * CH + ch;
    float s = 0.f, q = 0.f;
    if (X2) {
        const float* p2 = X2 + (size_t)chunk * 128 * CH + ch;
        for (int r = 0; r < 128; r++) {
            float v = p[(size_t)r * CH] + p2[(size_t)r * CH];
            s += v; q = fmaf(v, v, q);
        }
    } else {
        for (int r = 0; r < 128; r++) {
            float v = p[(size_t)r * CH];
            s += v; q = fmaf(v, v, q);
        }
    }
    psum[chunk * CH + ch] = s;
    psq[chunk * CH + ch] = q;
}

__global__ void bn_final_k(const float* __restrict__ psum, const float* __restrict__ psq,
                           const float* __restrict__ gamma, const float* __restrict__ beta,
                           float* __restrict__ scale, float* __restrict__ shift) {
    int ch = threadIdx.x;  // 512
    float s = 0.f, q = 0.f;
    for (int c = 0; c < 192; c++) { s += psum[c * CH + ch]; q += psq[c * CH + ch]; }
    float mu = s * (1.0f / NTOK);
    float var = q * (1.0f / NTOK) - mu * mu;
    float sc = gamma[ch] * rsqrtf(var + 1e-5f);
    scale[ch] = sc;
    shift[ch] = beta[ch] - mu * sc;
}

__global__ void bn_apply_k(float* __restrict__ Y, const float* __restrict__ X,
                           const float* __restrict__ X2,
                           const float* __restrict__ scale, const float* __restrict__ shift) {
    int i = blockIdx.x * blockDim.x + threadIdx.x;  // float4 index
    int ch4 = (i & 127) << 2;
    float4 x = reinterpret_cast<const float4*>(X)[i];
    if (X2) {
        float4 x2 = reinterpret_cast<const float4*>(X2)[i];
        x.x += x2.x; x.y += x2.y; x.z += x2.z; x.w += x2.w;
    }
    x.x = fmaf(x.x, scale[ch4 + 0], shift[ch4 + 0]);
    x.y = fmaf(x.y, scale[ch4 + 1], shift[ch4 + 1]);
    x.z = fmaf(x.z, scale[ch4 + 2], shift[ch4 + 2]);
    x.w = fmaf(x.w, scale[ch4 + 3], shift[ch4 + 3]);
    reinterpret_cast<float4*>(Y)[i] = x;
}

// ---------------- driver ----------------------------------------------------
extern "C" void kernel_launch(void* const* d_in, const int* in_sizes, int n_in,
                              void* d_out, int out_size) {
    const float* src    = (const float*)d_in[0];
    const float* qk_w   = (const float*)d_in[1];
    const float* qk_b   = (const float*)d_in[2];
    const float* v_w    = (const float*)d_in[3];
    const float* v_b    = (const float*)d_in[4];
    const float* alpha  = (const float*)d_in[5];
    const float* g_pre1 = (const float*)d_in[6];
    const float* b_pre1 = (const float*)d_in[7];
    const float* g_pre2 = (const float*)d_in[8];
    const float* b_pre2 = (const float*)d_in[9];
    const float* f1w1   = (const float*)d_in[10];
    const float* f1b1   = (const float*)d_in[11];
    const float* f1w2   = (const float*)d_in[12];
    const float* f1b2   = (const float*)d_in[13];
    const float* f2w1   = (const float*)d_in[14];
    const float* f2b1   = (const float*)d_in[15];
    const float* f2w2   = (const float*)d_in[16];
    const float* f2b2   = (const float*)d_in[17];
    const float* g_attn = (const float*)d_in[18];
    const float* b_attn = (const float*)d_in[19];
    float* out = (float*)d_out;

    float *S1, *QK, *Vb, *Q1, *K1, *OT, *OH, *HB, *ACC, *PS, *PQ, *SC, *SH;
    cudaGetSymbolAddress((void**)&S1,  g_s1);
    cudaGetSymbolAddress((void**)&QK,  g_qkbuf);
    cudaGetSymbolAddress((void**)&Vb,  g_vbuf);
    cudaGetSymbolAddress((void**)&Q1,  g_q1);
    cudaGetSymbolAddress((void**)&K1,  g_k1);
    cudaGetSymbolAddress((void**)&OT,  g_ot);
    cudaGetSymbolAddress((void**)&OH,  g_oh);
    cudaGetSymbolAddress((void**)&HB,  g_hbuf);
    cudaGetSymbolAddress((void**)&ACC, g_accb);
    cudaGetSymbolAddress((void**)&PS,  g_ps);
    cudaGetSymbolAddress((void**)&PQ,  g_pq);
    cudaGetSymbolAddress((void**)&SC,  g_scv);
    cudaGetSymbolAddress((void**)&SH,  g_shv);

    cudaFuncSetAttribute(tok_attn_k, cudaFuncAttributeMaxDynamicSharedMemorySize, 98304);
    cudaFuncSetAttribute(hid_attn_k, cudaFuncAttributeMaxDynamicSharedMemorySize, (24576 + 64 * SPAD) * 4);

    // 1. normalize src
    l2norm_k<<<NTOK, 128>>>(src, S1);
    // 2. projections
    sgemm_k<0><<<dim3(8, 192), 256>>>(S1, qk_w, qk_b, QK, NTOK, 1024, 512);
    sgemm_k<0><<<dim3(4, 192), 256>>>(src, v_w, v_b, Vb, NTOK, 512, 512);
    // 3. decay scan -> q1, k1 (head-major)
    decay_k<<<dim3(G, 2), 512>>>(QK, alpha, Q1, K1);
    // 4. attentions
    tok_attn_k<<<1024, 192, 98304>>>(Q1, K1, Vb, OT);
    hid_attn_k<<<1024, 256, (24576 + 64 * SPAD) * 4>>>(QK, Vb, OH);
    // 5. BN(out_tok) with pre2 -> o3 (in place)
    bn_partial_k<<<192, 512>>>(OT, nullptr, PS, PQ);
    bn_final_k<<<1, 512>>>(PS, PQ, g_pre2, b_pre2, SC, SH);
    bn_apply_k<<<NELEM / 4 / 256, 256>>>(OT, OT, nullptr, SC, SH);
    // 6. FF1: ACC = gelu(o3 @ w1^T + b1) @ w2^T + b2
    sgemm_k<1><<<dim3(16, 192), 256>>>(OT, f1w1, f1b1, HB, NTOK, DFFC, 512);
    sgemm_k<0><<<dim3(4, 192), 256>>>(HB, f1w2, f1b2, ACC, NTOK, 512, DFFC);
    // 7. BN(out_hid) with pre1 -> o2 (in place)
    bn_partial_k<<<192, 512>>>(OH, nullptr, PS, PQ);
    bn_final_k<<<1, 512>>>(PS, PQ, g_pre1, b_pre1, SC, SH);
    bn_apply_k<<<NELEM / 4 / 256, 256>>>(OH, OH, nullptr, SC, SH);
    // 8. FF2: ACC += gelu(o2 @ w1^T + b1) @ w2^T + b2
    sgemm_k<1><<<dim3(16, 192), 256>>>(OH, f2w1, f2b1, HB, NTOK, DFFC, 512);
    sgemm_k<2><<<dim3(4, 192), 256>>>(HB, f2w2, f2b2, ACC, NTOK, 512, DFFC);
    // 9. final BN(src + ACC) with g_attn/b_attn -> out
    bn_partial_k<<<192, 512>>>(src, ACC, PS, PQ);
    bn_final_k<<<1, 512>>>(PS, PQ, g_attn, b_attn, SC, SH);
    bn_apply_k<<<NELEM / 4 / 256, 256>>>(out, src, ACC, SC, SH);
}

// round 2
// speedup vs baseline: 1.5843x; 1.5843x over previous
#include <cuda_runtime.h>
#include <math.h>
#include <stdint.h>

#define G     128       // B*NV
#define HTOK  192
#define CH    512
#define NHD   8
#define HD    64
#define DFFC  2048
#define NTOK  24576     // G*HTOK
#define NELEM 12582912  // NTOK*CH

// ---------------- scratch (static device globals; allocation-free) ----------
__device__ float g_s1[NELEM];          // normalized src
__device__ float g_qkbuf[NTOK * 1024]; // qk projection
__device__ float g_vbuf[NELEM];        // v projection
__device__ float g_q1[NELEM];          // decayed q, head-major [head][t][d]
__device__ float g_k1[NELEM];          // decayed k
__device__ float g_ot[NELEM];          // token-attn out (head-major flat)
__device__ float g_oh[NELEM];          // hidden-attn out
__device__ float g_hbuf[NTOK * DFFC];  // FF hidden (reused)
__device__ float g_accb[NELEM];        // src2 accumulator
__device__ float g_ps[192 * 512];
__device__ float g_pq[192 * 512];
__device__ float g_scv[512];
__device__ float g_shv[512];

// ---------------- L2 normalize rows of 512 ---------------------------------
__global__ void l2norm_k(const float* __restrict__ X, float* __restrict__ Y) {
    __shared__ float red[4];
    int row = blockIdx.x;
    int tid = threadIdx.x;  // 128
    const float4* xp = reinterpret_cast<const float4*>(X + (size_t)row * CH);
    float4 v = xp[tid];
    float ss = v.x * v.x + v.y * v.y + v.z * v.z + v.w * v.w;
    #pragma unroll
    for (int o = 16; o > 0; o >>= 1) ss += __shfl_xor_sync(0xffffffffu, ss, o);
    if ((tid & 31) == 0) red[tid >> 5] = ss;
    __syncthreads();
    float rn = rsqrtf(red[0] + red[1] + red[2] + red[3]);
    v.x *= rn; v.y *= rn; v.z *= rn; v.w *= rn;
    reinterpret_cast<float4*>(Y + (size_t)row * CH)[tid] = v;
}

// ---------------- tf32 tensor-core GEMM: C = epi(A @ B^T + bias) ------------
// A [M,K] row-major, B [N,K] row-major. M = gridDim.y*128, N = gridDim.x*128.
// K % 32 == 0. EPI: 0 = store, 1 = exact GELU, 2 = accumulate into C.
__device__ __forceinline__ uint32_t f2tf32(float x) {
    uint32_t y;
    asm("cvt.rna.tf32.f32 %0, %1;" : "=r"(y) : "f"(x));
    return y;
}
__device__ __forceinline__ void mma_tf32(float* c, const uint32_t* a, const uint32_t* b) {
    asm volatile(
        "mma.sync.aligned.m16n8k8.row.col.f32.tf32.tf32.f32 "
        "{%0,%1,%2,%3}, {%4,%5,%6,%7}, {%8,%9}, {%0,%1,%2,%3};"
        : "+f"(c[0]), "+f"(c[1]), "+f"(c[2]), "+f"(c[3])
        : "r"(a[0]), "r"(a[1]), "r"(a[2]), "r"(a[3]), "r"(b[0]), "r"(b[1]));
}

template <int EPI>
__global__ void __launch_bounds__(256) tgemm_k(
    const float* __restrict__ A, const float* __restrict__ B,
    const float* __restrict__ bias, float* __restrict__ Cm,
    int N, int K) {
    // smem in fragment-permuted layout
    // A tiles: 32 tiles (kt*8+mt) of 128 floats; pos = lane*4 + reg
    // B tiles: 64 tiles (kt*16+nt) of 64 floats; pos = lane*2 + reg
    __shared__ float As[4096];
    __shared__ float Bs[4096];
    const int tid = threadIdx.x;
    const int bm = blockIdx.y * 128;
    const int bn = blockIdx.x * 128;
    const int wid = tid >> 5, lane = tid & 31;
    const int wm = wid >> 2, wn = wid & 3;   // warp grid 2 x 4 -> warp tile 64x32

    // staging: thread handles row sm_row (A-m and B-n), k-range [kq, kq+16)
    const int sm_row = tid >> 1;
    const int kq = (tid & 1) * 16;
    const float* Ap = A + (size_t)(bm + sm_row) * K + kq;
    const float* Bp = B + (size_t)(bn + sm_row) * K + kq;

    const int r_a = sm_row & 15;        // row within A m-tile
    const int mt_a = sm_row >> 4;       // A m-tile
    const int rn_b = sm_row & 7;        // row within B n-tile
    const int nt_b = sm_row >> 3;       // B n-tile

    float4 ra[4], rb[4];
    #pragma unroll
    for (int j = 0; j < 4; j++) {
        ra[j] = *reinterpret_cast<const float4*>(Ap + 4 * j);
        rb[j] = *reinterpret_cast<const float4*>(Bp + 4 * j);
    }

    float acc[4][4][4];
    #pragma unroll
    for (int mt = 0; mt < 4; mt++)
        #pragma unroll
        for (int nt = 0; nt < 4; nt++)
            #pragma unroll
            for (int i = 0; i < 4; i++) acc[mt][nt][i] = 0.f;

    for (int k0 = 0; k0 < K; k0 += 32) {
        __syncthreads();
        #pragma unroll
        for (int j = 0; j < 4; j++) {
            int kk = kq + 4 * j;       // 0..28
            int kt = kk >> 3;          // k-step
            int c0 = kk & 4;           // 0 or 4 within k-tile
            // A scatter: pos = ((r&7)*4+i)*4 + (r>>3) + 2*(c0>>2)
            float* pa = As + (kt * 8 + mt_a) * 128 + (r_a & 7) * 16 + (r_a >> 3) + (c0 >> 1);
            pa[0]  = __uint_as_float(f2tf32(ra[j].x));
            pa[4]  = __uint_as_float(f2tf32(ra[j].y));
            pa[8]  = __uint_as_float(f2tf32(ra[j].z));
            pa[12] = __uint_as_float(f2tf32(ra[j].w));
            // B scatter: pos = ((n&7)*4+i)*2 + (c0>>2)
            float* pb = Bs + (kt * 16 + nt_b) * 64 + rn_b * 8 + (c0 >> 2);
            pb[0] = __uint_as_float(f2tf32(rb[j].x));
            pb[2] = __uint_as_float(f2tf32(rb[j].y));
            pb[4] = __uint_as_float(f2tf32(rb[j].z));
            pb[6] = __uint_as_float(f2tf32(rb[j].w));
        }
        __syncthreads();
        if (k0 + 32 < K) {
            #pragma unroll
            for (int j = 0; j < 4; j++) {
                ra[j] = *reinterpret_cast<const float4*>(Ap + k0 + 32 + 4 * j);
                rb[j] = *reinterpret_cast<const float4*>(Bp + k0 + 32 + 4 * j);
            }
        }
        #pragma unroll
        for (int kt = 0; kt < 4; kt++) {
            uint32_t af[4][4];
            uint32_t bf[4][2];
            #pragma unroll
            for (int mt = 0; mt < 4; mt++) {
                float4 v = *reinterpret_cast<const float4*>(
                    As + (kt * 8 + wm * 4 + mt) * 128 + lane * 4);
                af[mt][0] = __float_as_uint(v.x);
                af[mt][1] = __float_as_uint(v.y);
                af[mt][2] = __float_as_uint(v.z);
                af[mt][3] = __float_as_uint(v.w);
            }
            #pragma unroll
            for (int nt = 0; nt < 4; nt++) {
                float2 v = *reinterpret_cast<const float2*>(
                    Bs + (kt * 16 + wn * 4 + nt) * 64 + lane * 2);
                bf[nt][0] = __float_as_uint(v.x);
                bf[nt][1] = __float_as_uint(v.y);
            }
            #pragma unroll
            for (int mt = 0; mt < 4; mt++)
                #pragma unroll
                for (int nt = 0; nt < 4; nt++)
                    mma_tf32(acc[mt][nt], af[mt], bf[nt]);
        }
    }

    // epilogue
    const int g = lane >> 2, tig = lane & 3;
    #pragma unroll
    for (int mt = 0; mt < 4; mt++) {
        int m0 = bm + wm * 64 + mt * 16 + g;
        #pragma unroll
        for (int nt = 0; nt < 4; nt++) {
            int n0 = bn + wn * 32 + nt * 8 + tig * 2;
            float b0 = bias[n0], b1 = bias[n0 + 1];
            float v00 = acc[mt][nt][0] + b0;
            float v01 = acc[mt][nt][1] + b1;
            float v10 = acc[mt][nt][2] + b0;
            float v11 = acc[mt][nt][3] + b1;
            float* C0 = Cm + (size_t)m0 * N + n0;
            float* C1 = Cm + (size_t)(m0 + 8) * N + n0;
            if (EPI == 1) {
                v00 = 0.5f * v00 * (1.0f + erff(v00 * 0.70710678118654752f));
                v01 = 0.5f * v01 * (1.0f + erff(v01 * 0.70710678118654752f));
                v10 = 0.5f * v10 * (1.0f + erff(v10 * 0.70710678118654752f));
                v11 = 0.5f * v11 * (1.0f + erff(v11 * 0.70710678118654752f));
            }
            if (EPI == 2) {
                float2 o0 = *reinterpret_cast<float2*>(C0);
                float2 o1 = *reinterpret_cast<float2*>(C1);
                v00 += o0.x; v01 += o0.y;
                v10 += o1.x; v11 += o1.y;
            }
            *reinterpret_cast<float2*>(C0) = make_float2(v00, v01);
            *reinterpret_cast<float2*>(C1) = make_float2(v10, v11);
        }
    }
}

// ---------------- exponential-decay scan (replaces FFT conv) ---------------
__global__ void decay_k(const float* __restrict__ QK, const float* __restrict__ alpha,
                        float* __restrict__ Q1, float* __restrict__ K1) {
    int g = blockIdx.x;      // 0..127
    int which = blockIdx.y;  // 0=q, 1=k
    int ch = threadIdx.x;    // 0..511
    int d = ch & 63;
    int nh = ch >> 6;
    float a = 1.f / (1.f + expf(-alpha[d]));
    float r = 1.f - a;
    float l2r = log2f(r);
    const float* x = QK + (size_t)g * (HTOK * 1024) + which * 512 + ch;
    float* y = (which ? K1 : Q1) + (size_t)g * (NHD * HTOK * HD) +
               (size_t)nh * (HTOK * HD) + d;
    float z = 0.f;
    for (int t = 0; t < HTOK; ++t) {
        z = fmaf(x[(size_t)t * 1024], exp2f((float)t * l2r), z);
        y[(size_t)t * 64] = a * exp2f((float)(HTOK - 1 - t) * l2r) * z;
    }
}

// ---------------- token attention: per head 192x64, online softmax ---------
__global__ void __launch_bounds__(192, 2) tok_attn_k(
    const float* __restrict__ Q1, const float* __restrict__ K1,
    const float* __restrict__ V, float* __restrict__ O) {
    extern __shared__ float sm[];
    float* Ks = sm;           // 12288
    float* Vs = sm + 12288;   // 12288
    int head = blockIdx.x;
    int g = head >> 3, nh = head & 7;
    int tid = threadIdx.x;
    const float4* Ksrc = reinterpret_cast<const float4*>(K1 + (size_t)head * 12288);
    float4* Kd = reinterpret_cast<float4*>(Ks);
    for (int i = tid; i < 3072; i += 192) Kd[i] = Ksrc[i];
    const float* Vbase = V + (size_t)g * HTOK * CH + nh * 64;
    for (int i = tid; i < 12288; i += 192) {
        int t = i >> 6, d = i & 63;
        Vs[i] = Vbase[(size_t)t * CH + d];
    }
    __syncthreads();
    int e = tid;
    float q[64];
    const float4* Qsrc = reinterpret_cast<const float4*>(Q1 + (size_t)head * 12288 + e * 64);
    #pragma unroll
    for (int j = 0; j < 16; j++) {
        float4 v4 = Qsrc[j];
        q[4*j] = v4.x; q[4*j+1] = v4.y; q[4*j+2] = v4.z; q[4*j+3] = v4.w;
    }
    float m = -1e30f, l = 0.f;
    float acc[64];
    #pragma unroll
    for (int j = 0; j < 64; j++) acc[j] = 0.f;
    for (int f = 0; f < HTOK; ++f) {
        const float4* kf = reinterpret_cast<const float4*>(Ks + f * 64);
        float s = 0.f;
        #pragma unroll
        for (int j = 0; j < 16; j++) {
            float4 kv = kf[j];
            s += q[4*j]*kv.x + q[4*j+1]*kv.y + q[4*j+2]*kv.z + q[4*j+3]*kv.w;
        }
        s *= 8.0f;  // * hd**0.5
        float mn = fmaxf(m, s);
        float corr = __expf(m - mn);
        float p = __expf(s - mn);
        l = l * corr + p;
        const float4* vf = reinterpret_cast<const float4*>(Vs + f * 64);
        #pragma unroll
        for (int j = 0; j < 16; j++) {
            float4 vv = vf[j];
            acc[4*j]   = acc[4*j]   * corr + p * vv.x;
            acc[4*j+1] = acc[4*j+1] * corr + p * vv.y;
            acc[4*j+2] = acc[4*j+2] * corr + p * vv.z;
            acc[4*j+3] = acc[4*j+3] * corr + p * vv.w;
        }
        m = mn;
    }
    float inv = 1.0f / l;
    float* Op = O + (size_t)head * 12288 + e * 64;
    #pragma unroll
    for (int d = 0; d < 64; d++) Op[d] = acc[d] * inv;
}

// ---------------- hidden attention: per head 64x64 over 192 ----------------
#define SPAD 65
__global__ void __launch_bounds__(256) hid_attn_k(
    const float* __restrict__ QK, const float* __restrict__ V,
    float* __restrict__ O) {
    extern __shared__ float sm[];
    float* qs = sm;            // 12288  (later reused for V)
    float* ks = sm + 12288;    // 12288
    float* ss = sm + 24576;    // 64*65
    int head = blockIdx.x;
    int g = head >> 3, nh = head & 7;
    int tid = threadIdx.x;
    const float* Qb = QK + (size_t)g * HTOK * 1024 + nh * 64;
    const float* Kb = Qb + 512;
    for (int i = tid; i < 12288; i += 256) {
        int a = i >> 6, e = i & 63;
        qs[i] = Qb[(size_t)a * 1024 + e];
        ks[i] = Kb[(size_t)a * 1024 + e];
    }
    __syncthreads();
    {
        int e = tid & 63;
        int f0 = (tid >> 6) << 4;  // 0,16,32,48
        float sacc[16];
        #pragma unroll
        for (int j = 0; j < 16; j++) sacc[j] = 0.f;
        for (int a = 0; a < HTOK; a++) {
            float qv = qs[a * 64 + e];
            const float* kr = ks + a * 64 + f0;
            #pragma unroll
            for (int j = 0; j < 16; j++) sacc[j] = fmaf(qv, kr[j], sacc[j]);
        }
        #pragma unroll
        for (int j = 0; j < 16; j++) ss[e * SPAD + f0 + j] = sacc[j] * 13.856406460551018f; // sqrt(192)
    }
    __syncthreads();
    if (tid < 64) {
        float* row = ss + tid * SPAD;
        float mx = row[0];
        #pragma unroll 8
        for (int f = 1; f < 64; f++) mx = fmaxf(mx, row[f]);
        float sum = 0.f;
        #pragma unroll 8
        for (int f = 0; f < 64; f++) { float p = __expf(row[f] - mx); row[f] = p; sum += p; }
        float inv = 1.0f / sum;
        #pragma unroll 8
        for (int f = 0; f < 64; f++) row[f] *= inv;
    }
    __syncthreads();
    const float* Vb = V + (size_t)g * HTOK * CH + nh * 64;
    for (int i = tid; i < 12288; i += 256) {
        int a = i >> 6, d = i & 63;
        qs[i] = Vb[(size_t)a * CH + d];
    }
    __syncthreads();
    float* Op = O + (size_t)head * 12288;
    for (int o = tid; o < 12288; o += 256) {
        int a = o >> 6, e = o & 63;
        const float* ar = ss + e * SPAD;
        const float* vr = qs + a * 64;
        float s = 0.f;
        #pragma unroll
        for (int f = 0; f < 64; f++) s = fmaf(ar[f], vr[f], s);
        Op[o] = s;
    }
}

// ---------------- BatchNorm (train-mode batch stats, per 512-channel) ------
__global__ void bn_partial_k(const float* __restrict__ X, const float* __restrict__ X2,
                             float* __restrict__ psum, float* __restrict__ psq) {
    int chunk = blockIdx.x;   // 192 chunks of 128 rows
    int ch = threadIdx.x;     // 512
    const float* p = X + (size_t)chunk * 128 * CH + ch;
    float s = 0.f, q = 0.f;
    if (X2) {
        const float* p2 = X2 + (size_t)chunk * 128 * CH + ch;
        for (int r = 0; r < 128; r++) {
            float v = p[(size_t)r * CH] + p2[(size_t)r * CH];
            s += v; q = fmaf(v, v, q);
        }
    } else {
        for (int r = 0; r < 128; r++) {
            float v = p[(size_t)r * CH];
            s += v; q = fmaf(v, v, q);
        }
    }
    psum[chunk * CH + ch] = s;
    psq[chunk * CH + ch] = q;
}

__global__ void bn_final_k(const float* __restrict__ psum, const float* __restrict__ psq,
                           const float* __restrict__ gamma, const float* __restrict__ beta,
                           float* __restrict__ scale, float* __restrict__ shift) {
    int ch = threadIdx.x;  // 512
    float s = 0.f, q = 0.f;
    for (int c = 0; c < 192; c++) { s += psum[c * CH + ch]; q += psq[c * CH + ch]; }
    float mu = s * (1.0f / NTOK);
    float var = q * (1.0f / NTOK) - mu * mu;
    float sc = gamma[ch] * rsqrtf(var + 1e-5f);
    scale[ch] = sc;
    shift[ch] = beta[ch] - mu * sc;
}

__global__ void bn_apply_k(float* __restrict__ Y, const float* __restrict__ X,
                           const float* __restrict__ X2,
                           const float* __restrict__ scale, const float* __restrict__ shift) {
    int i = blockIdx.x * blockDim.x + threadIdx.x;  // float4 index
    int ch4 = (i & 127) << 2;
    float4 x = reinterpret_cast<const float4*>(X)[i];
    if (X2) {
        float4 x2 = reinterpret_cast<const float4*>(X2)[i];
        x.x += x2.x; x.y += x2.y; x.z += x2.z; x.w += x2.w;
    }
    x.x = fmaf(x.x, scale[ch4 + 0], shift[ch4 + 0]);
    x.y = fmaf(x.y, scale[ch4 + 1], shift[ch4 + 1]);
    x.z = fmaf(x.z, scale[ch4 + 2], shift[ch4 + 2]);
    x.w = fmaf(x.w, scale[ch4 + 3], shift[ch4 + 3]);
    reinterpret_cast<float4*>(Y)[i] = x;
}

// ---------------- driver ----------------------------------------------------
extern "C" void kernel_launch(void* const* d_in, const int* in_sizes, int n_in,
                              void* d_out, int out_size) {
    const float* src    = (const float*)d_in[0];
    const float* qk_w   = (const float*)d_in[1];
    const float* qk_b   = (const float*)d_in[2];
    const float* v_w    = (const float*)d_in[3];
    const float* v_b    = (const float*)d_in[4];
    const float* alpha  = (const float*)d_in[5];
    const float* g_pre1 = (const float*)d_in[6];
    const float* b_pre1 = (const float*)d_in[7];
    const float* g_pre2 = (const float*)d_in[8];
    const float* b_pre2 = (const float*)d_in[9];
    const float* f1w1   = (const float*)d_in[10];
    const float* f1b1   = (const float*)d_in[11];
    const float* f1w2   = (const float*)d_in[12];
    const float* f1b2   = (const float*)d_in[13];
    const float* f2w1   = (const float*)d_in[14];
    const float* f2b1   = (const float*)d_in[15];
    const float* f2w2   = (const float*)d_in[16];
    const float* f2b2   = (const float*)d_in[17];
    const float* g_attn = (const float*)d_in[18];
    const float* b_attn = (const float*)d_in[19];
    float* out = (float*)d_out;

    float *S1, *QK, *Vb, *Q1, *K1, *OT, *OH, *HB, *ACC, *PS, *PQ, *SC, *SH;
    cudaGetSymbolAddress((void**)&S1,  g_s1);
    cudaGetSymbolAddress((void**)&QK,  g_qkbuf);
    cudaGetSymbolAddress((void**)&Vb,  g_vbuf);
    cudaGetSymbolAddress((void**)&Q1,  g_q1);
    cudaGetSymbolAddress((void**)&K1,  g_k1);
    cudaGetSymbolAddress((void**)&OT,  g_ot);
    cudaGetSymbolAddress((void**)&OH,  g_oh);
    cudaGetSymbolAddress((void**)&HB,  g_hbuf);
    cudaGetSymbolAddress((void**)&ACC, g_accb);
    cudaGetSymbolAddress((void**)&PS,  g_ps);
    cudaGetSymbolAddress((void**)&PQ,  g_pq);
    cudaGetSymbolAddress((void**)&SC,  g_scv);
    cudaGetSymbolAddress((void**)&SH,  g_shv);

    cudaFuncSetAttribute(tok_attn_k, cudaFuncAttributeMaxDynamicSharedMemorySize, 98304);
    cudaFuncSetAttribute(hid_attn_k, cudaFuncAttributeMaxDynamicSharedMemorySize, (24576 + 64 * SPAD) * 4);

    // 1. normalize src
    l2norm_k<<<NTOK, 128>>>(src, S1);
    // 2. projections (tf32 tensor cores)
    tgemm_k<0><<<dim3(8, 192), 256>>>(S1, qk_w, qk_b, QK, 1024, 512);
    tgemm_k<0><<<dim3(4, 192), 256>>>(src, v_w, v_b, Vb, 512, 512);
    // 3. decay scan -> q1, k1 (head-major)
    decay_k<<<dim3(G, 2), 512>>>(QK, alpha, Q1, K1);
    // 4. attentions
    tok_attn_k<<<1024, 192, 98304>>>(Q1, K1, Vb, OT);
    hid_attn_k<<<1024, 256, (24576 + 64 * SPAD) * 4>>>(QK, Vb, OH);
    // 5. BN(out_tok) with pre2 -> o3 (in place)
    bn_partial_k<<<192, 512>>>(OT, nullptr, PS, PQ);
    bn_final_k<<<1, 512>>>(PS, PQ, g_pre2, b_pre2, SC, SH);
    bn_apply_k<<<NELEM / 4 / 256, 256>>>(OT, OT, nullptr, SC, SH);
    // 6. FF1: ACC = gelu(o3 @ w1^T + b1) @ w2^T + b2
    tgemm_k<1><<<dim3(16, 192), 256>>>(OT, f1w1, f1b1, HB, 2048, 512);
    tgemm_k<0><<<dim3(4, 192), 256>>>(HB, f1w2, f1b2, ACC, 512, 2048);
    // 7. BN(out_hid) with pre1 -> o2 (in place)
    bn_partial_k<<<192, 512>>>(OH, nullptr, PS, PQ);
    bn_final_k<<<1, 512>>>(PS, PQ, g_pre1, b_pre1, SC, SH);
    bn_apply_k<<<NELEM / 4 / 256, 256>>>(OH, OH, nullptr, SC, SH);
    // 8. FF2: ACC += gelu(o2 @ w1^T + b1) @ w2^T + b2
    tgemm_k<1><<<dim3(16, 192), 256>>>(OH, f2w1, f2b1, HB, 2048, 512);
    tgemm_k<2><<<dim3(4, 192), 256>>>(HB, f2w2, f2b2, ACC, 512, 2048);
    // 9. final BN(src + ACC) with g_attn/b_attn -> out
    bn_partial_k<<<192, 512>>>(src, ACC, PS, PQ);
    bn_final_k<<<1, 512>>>(PS, PQ, g_attn, b_attn, SC, SH);
    bn_apply_k<<<NELEM / 4 / 256, 256>>>(out, src, ACC, SC, SH);
}

// round 4
// speedup vs baseline: 2.7954x; 1.7645x over previous
#include <cuda_runtime.h>
#include <math.h>
#include <stdint.h>

#define G     128       // B*NV
#define HTOK  192
#define CH    512
#define NHD   8
#define HD    64
#define DFFC  2048
#define NTOK  24576     // G*HTOK
#define NELEM 12582912  // NTOK*CH

// ---------------- scratch (static device globals; allocation-free) ----------
__device__ float g_s1[NELEM];          // normalized src
__device__ float g_qkbuf[NTOK * 1024]; // qk projection
__device__ float g_vbuf[NELEM];        // v projection
__device__ float g_q1[NELEM];          // decayed q, head-major [head][t][d]
__device__ float g_k1[NELEM];          // decayed k
__device__ float g_ot[NELEM];          // token-attn out (head-major flat)
__device__ float g_oh[NELEM];          // hidden-attn out
__device__ float g_hbuf[NTOK * DFFC];  // FF hidden (reused)
__device__ float g_accb[NELEM];        // src2 accumulator
__device__ float g_ps[192 * 512];
__device__ float g_pq[192 * 512];
__device__ float g_scv[512];
__device__ float g_shv[512];

__device__ __forceinline__ uint32_t smem_u32(const void* p) {
    uint32_t a;
    asm("{ .reg .u64 t; cvta.to.shared.u64 t, %1; cvt.u32.u64 %0, t; }"
        : "=r"(a) : "l"(p));
    return a;
}
__device__ __forceinline__ uint32_t f2tf32(float x) {
    uint32_t y;
    asm("cvt.rna.tf32.f32 %0, %1;" : "=r"(y) : "f"(x));
    return y;
}
__device__ __forceinline__ void mma_tf32(float* c, const uint32_t* a, const uint32_t* b) {
    asm volatile(
        "mma.sync.aligned.m16n8k8.row.col.f32.tf32.tf32.f32 "
        "{%0,%1,%2,%3}, {%4,%5,%6,%7}, {%8,%9}, {%0,%1,%2,%3};"
        : "+f"(c[0]), "+f"(c[1]), "+f"(c[2]), "+f"(c[3])
        : "r"(a[0]), "r"(a[1]), "r"(a[2]), "r"(a[3]), "r"(b[0]), "r"(b[1]));
}

// ============ tf32 mma.sync GEMM, cp.async 3-stage: C = epi(A@B^T + bias) ===
// A [M,K] rm, B [N,K] rm. CTA tile 128x128. 1D grid = 192 * gridN, swizzled.
// K % 32 == 0. EPI: 0 = store, 1 = exact GELU, 2 = accumulate into C.
#define AROW 36
#define STG_FLOATS (2 * 128 * AROW)   // 9216 floats (A then B)
#define STG_BYTES  (STG_FLOATS * 4)   // 36864

template <int EPI>
__global__ void __launch_bounds__(256, 2) tgemm2_k(
    const float* __restrict__ A, const float* __restrict__ B,
    const float* __restrict__ bias, float* __restrict__ Cm,
    int N, int K, int gridN) {
    extern __shared__ float sm[];
    const int tid = threadIdx.x;
    const int wid = tid >> 5, lane = tid & 31;
    const int wm = wid >> 2, wn = wid & 3;     // 2x4 warps, warp tile 64x32
    const int g = lane >> 2, tig = lane & 3;

    // block swizzle: groups of 8 m-blocks sweep all n-blocks (L2 reuse)
    int bid = blockIdx.x;
    int per = 8 * gridN;
    int grp = bid / per, rem = bid - grp * per;
    const int bm = (grp * 8 + (rem & 7)) * 128;
    const int bn = (rem >> 3) * 128;

    const uint32_t sb = smem_u32(sm);
    const int CCH = K >> 5;

    // --- async copy of one K=32 chunk into stage s ---
    const int seg_row = tid >> 3;        // reused mapping: seg = i*256+tid
    const int seg_kq = tid & 7;
    #define CPY(c, s) do {                                                     \
        int _kc = (c) << 5;                                                    \
        uint32_t _sa = sb + (uint32_t)(s) * STG_BYTES;                         \
        _Pragma("unroll")                                                      \
        for (int _i = 0; _i < 4; _i++) {                                       \
            int _row = seg_row + _i * 32;                                      \
            uint32_t _off = (uint32_t)_row * 144u + (uint32_t)seg_kq * 16u;    \
            const float* _ga = A + (size_t)(bm + _row) * K + _kc + seg_kq * 4; \
            asm volatile("cp.async.cg.shared.global [%0], [%1], 16;"           \
                         :: "r"(_sa + _off), "l"(_ga));                        \
            const float* _gb = B + (size_t)(bn + _row) * K + _kc + seg_kq * 4; \
            asm volatile("cp.async.cg.shared.global [%0], [%1], 16;"           \
                         :: "r"(_sa + 18432u + _off), "l"(_gb));               \
        }                                                                      \
    } while (0)

    CPY(0, 0);
    asm volatile("cp.async.commit_group;" ::: "memory");
    CPY(1, 1);
    asm volatile("cp.async.commit_group;" ::: "memory");

    float acc[4][4][4];
    #pragma unroll
    for (int mt = 0; mt < 4; mt++)
        #pragma unroll
        for (int nt = 0; nt < 4; nt++)
            #pragma unroll
            for (int i = 0; i < 4; i++) acc[mt][nt][i] = 0.f;

    asm volatile("cp.async.wait_group 1;" ::: "memory");
    __syncthreads();

    const int arow0 = wm * 64 + g;
    const int brow0 = wn * 32 + g;

    for (int c = 0; c < CCH; c++) {
        int rs = c % 3;
        if (c + 2 < CCH) {
            int ws = rs + 2; if (ws >= 3) ws -= 3;
            CPY(c + 2, ws);
        }
        asm volatile("cp.async.commit_group;" ::: "memory");

        const float* As_ = sm + rs * STG_FLOATS;
        const float* Bs_ = As_ + 128 * AROW;
        #pragma unroll
        for (int kt = 0; kt < 4; kt++) {
            const int k0 = kt * 8 + tig;
            uint32_t af[4][4], bf[4][2];
            #pragma unroll
            for (int mt = 0; mt < 4; mt++) {
                const float* p = As_ + (arow0 + mt * 16) * AROW + k0;
                af[mt][0] = f2tf32(p[0]);
                af[mt][1] = f2tf32(p[8 * AROW]);
                af[mt][2] = f2tf32(p[4]);
                af[mt][3] = f2tf32(p[8 * AROW + 4]);
            }
            #pragma unroll
            for (int nt = 0; nt < 4; nt++) {
                const float* p = Bs_ + (brow0 + nt * 8) * AROW + k0;
                bf[nt][0] = f2tf32(p[0]);
                bf[nt][1] = f2tf32(p[4]);
            }
            #pragma unroll
            for (int mt = 0; mt < 4; mt++)
                #pragma unroll
                for (int nt = 0; nt < 4; nt++)
                    mma_tf32(acc[mt][nt], af[mt], bf[nt]);
        }
        asm volatile("cp.async.wait_group 1;" ::: "memory");
        __syncthreads();
    }

    // epilogue
    #pragma unroll
    for (int mt = 0; mt < 4; mt++) {
        int m0 = bm + wm * 64 + mt * 16 + g;
        #pragma unroll
        for (int nt = 0; nt < 4; nt++) {
            int n0 = bn + wn * 32 + nt * 8 + tig * 2;
            float b0 = bias[n0], b1 = bias[n0 + 1];
            float v00 = acc[mt][nt][0] + b0;
            float v01 = acc[mt][nt][1] + b1;
            float v10 = acc[mt][nt][2] + b0;
            float v11 = acc[mt][nt][3] + b1;
            float* C0 = Cm + (size_t)m0 * N + n0;
            float* C1 = Cm + (size_t)(m0 + 8) * N + n0;
            if (EPI == 1) {
                v00 = 0.5f * v00 * (1.0f + erff(v00 * 0.70710678118654752f));
                v01 = 0.5f * v01 * (1.0f + erff(v01 * 0.70710678118654752f));
                v10 = 0.5f * v10 * (1.0f + erff(v10 * 0.70710678118654752f));
                v11 = 0.5f * v11 * (1.0f + erff(v11 * 0.70710678118654752f));
            }
            if (EPI == 2) {
                float2 o0 = *reinterpret_cast<float2*>(C0);
                float2 o1 = *reinterpret_cast<float2*>(C1);
                v00 += o0.x; v01 += o0.y;
                v10 += o1.x; v11 += o1.y;
            }
            *reinterpret_cast<float2*>(C0) = make_float2(v00, v01);
            *reinterpret_cast<float2*>(C1) = make_float2(v10, v11);
        }
    }
}

// ---------------- L2 normalize rows of 512 ---------------------------------
__global__ void l2norm_k(const float* __restrict__ X, float* __restrict__ Y) {
    __shared__ float red[4];
    int row = blockIdx.x;
    int tid = threadIdx.x;  // 128
    const float4* xp = reinterpret_cast<const float4*>(X + (size_t)row * CH);
    float4 v = xp[tid];
    float ss = v.x * v.x + v.y * v.y + v.z * v.z + v.w * v.w;
    #pragma unroll
    for (int o = 16; o > 0; o >>= 1) ss += __shfl_xor_sync(0xffffffffu, ss, o);
    if ((tid & 31) == 0) red[tid >> 5] = ss;
    __syncthreads();
    float rn = rsqrtf(red[0] + red[1] + red[2] + red[3]);
    v.x *= rn; v.y *= rn; v.z *= rn; v.w *= rn;
    reinterpret_cast<float4*>(Y + (size_t)row * CH)[tid] = v;
}

// ---------------- exponential-decay scan (replaces FFT conv) ---------------
__global__ void decay_k(const float* __restrict__ QK, const float* __restrict__ alpha,
                        float* __restrict__ Q1, float* __restrict__ K1) {
    int g = blockIdx.x;      // 0..127
    int which = blockIdx.y;  // 0=q, 1=k
    int ch = threadIdx.x;    // 0..511
    int d = ch & 63;
    int nh = ch >> 6;
    float a = 1.f / (1.f + expf(-alpha[d]));
    float r = 1.f - a;
    float l2r = log2f(r);
    const float* x = QK + (size_t)g * (HTOK * 1024) + which * 512 + ch;
    float* y = (which ? K1 : Q1) + (size_t)g * (NHD * HTOK * HD) +
               (size_t)nh * (HTOK * HD) + d;
    float z = 0.f;
    for (int t = 0; t < HTOK; ++t) {
        z = fmaf(x[(size_t)t * 1024], exp2f((float)t * l2r), z);
        y[(size_t)t * 64] = a * exp2f((float)(HTOK - 1 - t) * l2r) * z;
    }
}

// ---------------- token attention: per head 192x64, online softmax ---------
__global__ void __launch_bounds__(192, 2) tok_attn_k(
    const float* __restrict__ Q1, const float* __restrict__ K1,
    const float* __restrict__ V, float* __restrict__ O) {
    extern __shared__ float sm[];
    float* Ks = sm;           // 12288
    float* Vs = sm + 12288;   // 12288
    int head = blockIdx.x;
    int g = head >> 3, nh = head & 7;
    int tid = threadIdx.x;
    const float4* Ksrc = reinterpret_cast<const float4*>(K1 + (size_t)head * 12288);
    float4* Kd = reinterpret_cast<float4*>(Ks);
    for (int i = tid; i < 3072; i += 192) Kd[i] = Ksrc[i];
    const float* Vbase = V + (size_t)g * HTOK * CH + nh * 64;
    for (int i = tid; i < 12288; i += 192) {
        int t = i >> 6, d = i & 63;
        Vs[i] = Vbase[(size_t)t * CH + d];
    }
    __syncthreads();
    int e = tid;
    float q[64];
    const float4* Qsrc = reinterpret_cast<const float4*>(Q1 + (size_t)head * 12288 + e * 64);
    #pragma unroll
    for (int j = 0; j < 16; j++) {
        float4 v4 = Qsrc[j];
        q[4*j] = v4.x; q[4*j+1] = v4.y; q[4*j+2] = v4.z; q[4*j+3] = v4.w;
    }
    float m = -1e30f, l = 0.f;
    float acc[64];
    #pragma unroll
    for (int j = 0; j < 64; j++) acc[j] = 0.f;
    for (int f = 0; f < HTOK; ++f) {
        const float4* kf = reinterpret_cast<const float4*>(Ks + f * 64);
        float s = 0.f;
        #pragma unroll
        for (int j = 0; j < 16; j++) {
            float4 kv = kf[j];
            s += q[4*j]*kv.x + q[4*j+1]*kv.y + q[4*j+2]*kv.z + q[4*j+3]*kv.w;
        }
        s *= 8.0f;  // * hd**0.5
        float mn = fmaxf(m, s);
        float corr = __expf(m - mn);
        float p = __expf(s - mn);
        l = l * corr + p;
        const float4* vf = reinterpret_cast<const float4*>(Vs + f * 64);
        #pragma unroll
        for (int j = 0; j < 16; j++) {
            float4 vv = vf[j];
            acc[4*j]   = acc[4*j]   * corr + p * vv.x;
            acc[4*j+1] = acc[4*j+1] * corr + p * vv.y;
            acc[4*j+2] = acc[4*j+2] * corr + p * vv.z;
            acc[4*j+3] = acc[4*j+3] * corr + p * vv.w;
        }
        m = mn;
    }
    float inv = 1.0f / l;
    float* Op = O + (size_t)head * 12288 + e * 64;
    #pragma unroll
    for (int d = 0; d < 64; d++) Op[d] = acc[d] * inv;
}

// ---------------- hidden attention: per head 64x64 over 192 ----------------
#define SPAD 65
__global__ void __launch_bounds__(256) hid_attn_k(
    const float* __restrict__ QK, const float* __restrict__ V,
    float* __restrict__ O) {
    extern __shared__ float sm[];
    float* qs = sm;            // 12288  (later reused for V)
    float* ks = sm + 12288;    // 12288
    float* ss = sm + 24576;    // 64*65
    int head = blockIdx.x;
    int g = head >> 3, nh = head & 7;
    int tid = threadIdx.x;
    const float* Qb = QK + (size_t)g * HTOK * 1024 + nh * 64;
    const float* Kb = Qb + 512;
    for (int i = tid; i < 12288; i += 256) {
        int a = i >> 6, e = i & 63;
        qs[i] = Qb[(size_t)a * 1024 + e];
        ks[i] = Kb[(size_t)a * 1024 + e];
    }
    __syncthreads();
    {
        int e = tid & 63;
        int f0 = (tid >> 6) << 4;  // 0,16,32,48
        float sacc[16];
        #pragma unroll
        for (int j = 0; j < 16; j++) sacc[j] = 0.f;
        for (int a = 0; a < HTOK; a++) {
            float qv = qs[a * 64 + e];
            const float* kr = ks + a * 64 + f0;
            #pragma unroll
            for (int j = 0; j < 16; j++) sacc[j] = fmaf(qv, kr[j], sacc[j]);
        }
        #pragma unroll
        for (int j = 0; j < 16; j++) ss[e * SPAD + f0 + j] = sacc[j] * 13.856406460551018f; // sqrt(192)
    }
    __syncthreads();
    if (tid < 64) {
        float* row = ss + tid * SPAD;
        float mx = row[0];
        #pragma unroll 8
        for (int f = 1; f < 64; f++) mx = fmaxf(mx, row[f]);
        float sum = 0.f;
        #pragma unroll 8
        for (int f = 0; f < 64; f++) { float p = __expf(row[f] - mx); row[f] = p; sum += p; }
        float inv = 1.0f / sum;
        #pragma unroll 8
        for (int f = 0; f < 64; f++) row[f] *= inv;
    }
    __syncthreads();
    const float* Vb = V + (size_t)g * HTOK * CH + nh * 64;
    for (int i = tid; i < 12288; i += 256) {
        int a = i >> 6, d = i & 63;
        qs[i] = Vb[(size_t)a * CH + d];
    }
    __syncthreads();
    float* Op = O + (size_t)head * 12288;
    for (int o = tid; o < 12288; o += 256) {
        int a = o >> 6, e = o & 63;
        const float* ar = ss + e * SPAD;
        const float* vr = qs + a * 64;
        float s = 0.f;
        #pragma unroll
        for (int f = 0; f < 64; f++) s = fmaf(ar[f], vr[f], s);
        Op[o] = s;
    }
}

// ---------------- BatchNorm (train-mode batch stats, per 512-channel) ------
__global__ void bn_partial_k(const float* __restrict__ X, const float* __restrict__ X2,
                             float* __restrict__ psum, float* __restrict__ psq) {
    int chunk = blockIdx.x;   // 192 chunks of 128 rows
    int ch = threadIdx.x;     // 512
    const float* p = X + (size_t)chunk * 128 * CH + ch;
    float s = 0.f, q = 0.f;
    if (X2) {
        const float* p2 = X2 + (size_t)chunk * 128 * CH + ch;
        for (int r = 0; r < 128; r++) {
            float v = p[(size_t)r * CH] + p2[(size_t)r * CH];
            s += v; q = fmaf(v, v, q);
        }
    } else {
        for (int r = 0; r < 128; r++) {
            float v = p[(size_t)r * CH];
            s += v; q = fmaf(v, v, q);
        }
    }
    psum[chunk * CH + ch] = s;
    psq[chunk * CH + ch] = q;
}

__global__ void bn_final_k(const float* __restrict__ psum, const float* __restrict__ psq,
                           const float* __restrict__ gamma, const float* __restrict__ beta,
                           float* __restrict__ scale, float* __restrict__ shift) {
    int ch = threadIdx.x;  // 512
    float s = 0.f, q = 0.f;
    for (int c = 0; c < 192; c++) { s += psum[c * CH + ch]; q += psq[c * CH + ch]; }
    float mu = s * (1.0f / NTOK);
    float var = q * (1.0f / NTOK) - mu * mu;
    float sc = gamma[ch] * rsqrtf(var + 1e-5f);
    scale[ch] = sc;
    shift[ch] = beta[ch] - mu * sc;
}

__global__ void bn_apply_k(float* __restrict__ Y, const float* __restrict__ X,
                           const float* __restrict__ X2,
                           const float* __restrict__ scale, const float* __restrict__ shift) {
    int i = blockIdx.x * blockDim.x + threadIdx.x;  // float4 index
    int ch4 = (i & 127) << 2;
    float4 x = reinterpret_cast<const float4*>(X)[i];
    if (X2) {
        float4 x2 = reinterpret_cast<const float4*>(X2)[i];
        x.x += x2.x; x.y += x2.y; x.z += x2.z; x.w += x2.w;
    }
    x.x = fmaf(x.x, scale[ch4 + 0], shift[ch4 + 0]);
    x.y = fmaf(x.y, scale[ch4 + 1], shift[ch4 + 1]);
    x.z = fmaf(x.z, scale[ch4 + 2], shift[ch4 + 2]);
    x.w = fmaf(x.w, scale[ch4 + 3], shift[ch4 + 3]);
    reinterpret_cast<float4*>(Y)[i] = x;
}

// ---------------- driver ----------------------------------------------------
extern "C" void kernel_launch(void* const* d_in, const int* in_sizes, int n_in,
                              void* d_out, int out_size) {
    const float* src    = (const float*)d_in[0];
    const float* qk_w   = (const float*)d_in[1];
    const float* qk_b   = (const float*)d_in[2];
    const float* v_w    = (const float*)d_in[3];
    const float* v_b    = (const float*)d_in[4];
    const float* alpha  = (const float*)d_in[5];
    const float* g_pre1 = (const float*)d_in[6];
    const float* b_pre1 = (const float*)d_in[7];
    const float* g_pre2 = (const float*)d_in[8];
    const float* b_pre2 = (const float*)d_in[9];
    const float* f1w1   = (const float*)d_in[10];
    const float* f1b1   = (const float*)d_in[11];
    const float* f1w2   = (const float*)d_in[12];
    const float* f1b2   = (const float*)d_in[13];
    const float* f2w1   = (const float*)d_in[14];
    const float* f2b1   = (const float*)d_in[15];
    const float* f2w2   = (const float*)d_in[16];
    const float* f2b2   = (const float*)d_in[17];
    const float* g_attn = (const float*)d_in[18];
    const float* b_attn = (const float*)d_in[19];
    float* out = (float*)d_out;

    float *S1, *QK, *Vb, *Q1, *K1, *OT, *OH, *HB, *ACC, *PS, *PQ, *SC, *SH;
    cudaGetSymbolAddress((void**)&S1,  g_s1);
    cudaGetSymbolAddress((void**)&QK,  g_qkbuf);
    cudaGetSymbolAddress((void**)&Vb,  g_vbuf);
    cudaGetSymbolAddress((void**)&Q1,  g_q1);
    cudaGetSymbolAddress((void**)&K1,  g_k1);
    cudaGetSymbolAddress((void**)&OT,  g_ot);
    cudaGetSymbolAddress((void**)&OH,  g_oh);
    cudaGetSymbolAddress((void**)&HB,  g_hbuf);
    cudaGetSymbolAddress((void**)&ACC, g_accb);
    cudaGetSymbolAddress((void**)&PS,  g_ps);
    cudaGetSymbolAddress((void**)&PQ,  g_pq);
    cudaGetSymbolAddress((void**)&SC,  g_scv);
    cudaGetSymbolAddress((void**)&SH,  g_shv);

    const int GSM = 3 * STG_BYTES;  // 110592 B
    cudaFuncSetAttribute(tgemm2_k<0>, cudaFuncAttributeMaxDynamicSharedMemorySize, GSM);
    cudaFuncSetAttribute(tgemm2_k<1>, cudaFuncAttributeMaxDynamicSharedMemorySize, GSM);
    cudaFuncSetAttribute(tgemm2_k<2>, cudaFuncAttributeMaxDynamicSharedMemorySize, GSM);
    cudaFuncSetAttribute(tok_attn_k, cudaFuncAttributeMaxDynamicSharedMemorySize, 98304);
    cudaFuncSetAttribute(hid_attn_k, cudaFuncAttributeMaxDynamicSharedMemorySize, (24576 + 64 * SPAD) * 4);

    // 1. normalize src
    l2norm_k<<<NTOK, 128>>>(src, S1);
    // 2. projections
    tgemm2_k<0><<<192 * 8, 256, GSM>>>(S1, qk_w, qk_b, QK, 1024, 512, 8);
    tgemm2_k<0><<<192 * 4, 256, GSM>>>(src, v_w, v_b, Vb, 512, 512, 4);
    // 3. decay scan -> q1, k1 (head-major)
    decay_k<<<dim3(G, 2), 512>>>(QK, alpha, Q1, K1);
    // 4. attentions
    tok_attn_k<<<1024, 192, 98304>>>(Q1, K1, Vb, OT);
    hid_attn_k<<<1024, 256, (24576 + 64 * SPAD) * 4>>>(QK, Vb, OH);
    // 5. BN(out_tok) with pre2 -> o3 (in place)
    bn_partial_k<<<192, 512>>>(OT, nullptr, PS, PQ);
    bn_final_k<<<1, 512>>>(PS, PQ, g_pre2, b_pre2, SC, SH);
    bn_apply_k<<<NELEM / 4 / 256, 256>>>(OT, OT, nullptr, SC, SH);
    // 6. FF1: ACC = gelu(o3 @ w1^T + b1) @ w2^T + b2
    tgemm2_k<1><<<192 * 16, 256, GSM>>>(OT, f1w1, f1b1, HB, 2048, 512, 16);
    tgemm2_k<0><<<192 * 4, 256, GSM>>>(HB, f1w2, f1b2, ACC, 512, 2048, 4);
    // 7. BN(out_hid) with pre1 -> o2 (in place)
    bn_partial_k<<<192, 512>>>(OH, nullptr, PS, PQ);
    bn_final_k<<<1, 512>>>(PS, PQ, g_pre1, b_pre1, SC, SH);
    bn_apply_k<<<NELEM / 4 / 256, 256>>>(OH, OH, nullptr, SC, SH);
    // 8. FF2: ACC += gelu(o2 @ w1^T + b1) @ w2^T + b2
    tgemm2_k<1><<<192 * 16, 256, GSM>>>(OH, f2w1, f2b1, HB, 2048, 512, 16);
    tgemm2_k<2><<<192 * 4, 256, GSM>>>(HB, f2w2, f2b2, ACC, 512, 2048, 4);
    // 9. final BN(src + ACC) with g_attn/b_attn -> out
    bn_partial_k<<<192, 512>>>(src, ACC, PS, PQ);
    bn_final_k<<<1, 512>>>(PS, PQ, g_attn, b_attn, SC, SH);
    bn_apply_k<<<NELEM / 4 / 256, 256>>>(out, src, ACC, SC, SH);
}

// round 5
// speedup vs baseline: 4.2070x; 1.5050x over previous
#include <cuda_runtime.h>
#include <cuda_fp16.h>
#include <math.h>
#include <stdint.h>

#define G     128       // B*NV
#define HTOK  192
#define CH    512
#define NHD   8
#define HD    64
#define DFFC  2048
#define NTOK  24576     // G*HTOK
#define NELEM 12582912  // NTOK*CH

// ---------------- scratch (static device globals; allocation-free) ----------
__device__ float g_qkbuf[NTOK * 1024]; // qk projection (fp32, feeds decay/hid_attn)
__device__ float g_vbuf[NELEM];        // v projection
__device__ float g_q1[NELEM];          // decayed q, head-major
__device__ float g_k1[NELEM];          // decayed k
__device__ float g_ot[NELEM];          // token-attn out
__device__ float g_oh[NELEM];          // hidden-attn out
__device__ float g_accb[NELEM];        // src2 accumulator
__device__ float g_ps[192 * 512];
__device__ float g_pq[192 * 512];
__device__ float g_scv[512];
__device__ float g_shv[512];
// fp16 operand buffers
__device__ __half g_s1h[NELEM];          // normalized src (half)
__device__ __half g_srch[NELEM];         // src (half)
__device__ __half g_oth[NELEM];          // BN(o3) half
__device__ __half g_ohh[NELEM];          // BN(o2) half
__device__ __half g_hbh[NTOK * DFFC];    // FF hidden (half)
__device__ __half g_wqk[1024 * 512];
__device__ __half g_wv[512 * 512];
__device__ __half g_w11[2048 * 512];
__device__ __half g_w12[512 * 2048];
__device__ __half g_w21[2048 * 512];
__device__ __half g_w22[512 * 2048];

__device__ __forceinline__ uint32_t smem_u32(const void* p) {
    uint32_t a;
    asm("{ .reg .u64 t; cvta.to.shared.u64 t, %1; cvt.u32.u64 %0, t; }"
        : "=r"(a) : "l"(p));
    return a;
}
__device__ __forceinline__ void mma_f16(float* c, const uint32_t* a, const uint32_t* b) {
    asm volatile(
        "mma.sync.aligned.m16n8k16.row.col.f32.f16.f16.f32 "
        "{%0,%1,%2,%3}, {%4,%5,%6,%7}, {%8,%9}, {%0,%1,%2,%3};"
        : "+f"(c[0]), "+f"(c[1]), "+f"(c[2]), "+f"(c[3])
        : "r"(a[0]), "r"(a[1]), "r"(a[2]), "r"(a[3]), "r"(b[0]), "r"(b[1]));
}

// ============ fp16 mma GEMM, cp.async 3-stage: C = epi(A@B^T + bias) ========
// A [M,K] half rm, B [N,K] half rm. CTA tile 128x128, K-chunk 64.
// EPI: 0 = store fp32, 1 = exact GELU -> half, 2 = accumulate fp32.
#define RSB 144                       // smem row stride bytes (64 halves + pad)
#define HSTG_BYTES (2 * 128 * RSB)    // 36864 per stage (A then B)

template <int EPI>
__global__ void __launch_bounds__(256, 2) hgemm_k(
    const __half* __restrict__ A, const __half* __restrict__ B,
    const float* __restrict__ bias, void* __restrict__ Cv,
    int N, int K, int gridN) {
    extern __shared__ char hsm[];
    const int tid = threadIdx.x;
    const int wid = tid >> 5, lane = tid & 31;
    const int wm = wid >> 2, wn = wid & 3;     // 2x4 warps, warp tile 64x32
    const int g = lane >> 2, tig = lane & 3;

    int bid = blockIdx.x;
    int per = 8 * gridN;
    int grp = bid / per, rem = bid - grp * per;
    const int bm = (grp * 8 + (rem & 7)) * 128;
    const int bn = (rem >> 3) * 128;

    const uint32_t sbase = smem_u32(hsm);
    const int CCH = K >> 6;

    const int c_row = tid >> 3;   // 0..31 (+32*i)
    const int c_cq = tid & 7;     // 16B chunk within 128B row
    #define CPYH(c, s) do {                                                     \
        int _kc = (c) << 6;                                                     \
        uint32_t _sa = sbase + (uint32_t)(s) * HSTG_BYTES;                      \
        _Pragma("unroll")                                                       \
        for (int _i = 0; _i < 4; _i++) {                                        \
            int _row = c_row + _i * 32;                                         \
            uint32_t _off = (uint32_t)_row * RSB + (uint32_t)c_cq * 16u;        \
            const __half* _ga = A + (size_t)(bm + _row) * K + _kc + c_cq * 8;   \
            asm volatile("cp.async.cg.shared.global [%0], [%1], 16;"            \
                         :: "r"(_sa + _off), "l"(_ga));                         \
            const __half* _gb = B + (size_t)(bn + _row) * K + _kc + c_cq * 8;   \
            asm volatile("cp.async.cg.shared.global [%0], [%1], 16;"            \
                         :: "r"(_sa + 18432u + _off), "l"(_gb));                \
        }                                                                       \
    } while (0)

    CPYH(0, 0);
    asm volatile("cp.async.commit_group;" ::: "memory");
    CPYH(1, 1);
    asm volatile("cp.async.commit_group;" ::: "memory");

    float acc[4][4][4];
    #pragma unroll
    for (int mt = 0; mt < 4; mt++)
        #pragma unroll
        for (int nt = 0; nt < 4; nt++)
            #pragma unroll
            for (int i = 0; i < 4; i++) acc[mt][nt][i] = 0.f;

    asm volatile("cp.async.wait_group 1;" ::: "memory");
    __syncthreads();

    // ldmatrix lane address offsets
    const int lr = lane & 7, sel = lane >> 3;
    // A x4: rows (sel&1)*8 + lr, col halves (sel>>1)*8
    const uint32_t aoff =
        (uint32_t)(wm * 64 + (sel & 1) * 8 + lr) * RSB + (uint32_t)((sel >> 1) * 8) * 2;
    // B x2: rows lr, col halves (sel&1)*8
    const uint32_t boff =
        (uint32_t)(wn * 32 + lr) * RSB + (uint32_t)((sel & 1) * 8) * 2;

    for (int c = 0; c < CCH; c++) {
        int rs = c % 3;
        if (c + 2 < CCH) {
            int ws = rs + 2; if (ws >= 3) ws -= 3;
            CPYH(c + 2, ws);
        }
        asm volatile("cp.async.commit_group;" ::: "memory");

        uint32_t sA = sbase + (uint32_t)rs * HSTG_BYTES;
        uint32_t sB = sA + 18432u;
        #pragma unroll
        for (int kt = 0; kt < 4; kt++) {
            uint32_t af[4][4], bf[4][2];
            #pragma unroll
            for (int mt = 0; mt < 4; mt++) {
                uint32_t ad = sA + aoff + (uint32_t)(mt * 16) * RSB + (uint32_t)kt * 32u;
                asm volatile(
                    "ldmatrix.sync.aligned.m8n8.x4.shared.b16 {%0,%1,%2,%3}, [%4];"
                    : "=r"(af[mt][0]), "=r"(af[mt][1]), "=r"(af[mt][2]), "=r"(af[mt][3])
                    : "r"(ad));
            }
            #pragma unroll
            for (int nt = 0; nt < 4; nt++) {
                uint32_t bd = sB + boff + (uint32_t)(nt * 8) * RSB + (uint32_t)kt * 32u;
                asm volatile(
                    "ldmatrix.sync.aligned.m8n8.x2.shared.b16 {%0,%1}, [%2];"
                    : "=r"(bf[nt][0]), "=r"(bf[nt][1])
                    : "r"(bd));
            }
            #pragma unroll
            for (int mt = 0; mt < 4; mt++)
                #pragma unroll
                for (int nt = 0; nt < 4; nt++)
                    mma_f16(acc[mt][nt], af[mt], bf[nt]);
        }
        asm volatile("cp.async.wait_group 1;" ::: "memory");
        __syncthreads();
    }

    // epilogue
    #pragma unroll
    for (int mt = 0; mt < 4; mt++) {
        int m0 = bm + wm * 64 + mt * 16 + g;
        #pragma unroll
        for (int nt = 0; nt < 4; nt++) {
            int n0 = bn + wn * 32 + nt * 8 + tig * 2;
            float b0 = bias[n0], b1 = bias[n0 + 1];
            float v00 = acc[mt][nt][0] + b0;
            float v01 = acc[mt][nt][1] + b1;
            float v10 = acc[mt][nt][2] + b0;
            float v11 = acc[mt][nt][3] + b1;
            if (EPI == 1) {
                v00 = 0.5f * v00 * (1.0f + erff(v00 * 0.70710678118654752f));
                v01 = 0.5f * v01 * (1.0f + erff(v01 * 0.70710678118654752f));
                v10 = 0.5f * v10 * (1.0f + erff(v10 * 0.70710678118654752f));
                v11 = 0.5f * v11 * (1.0f + erff(v11 * 0.70710678118654752f));
                __half* Ch = (__half*)Cv;
                *reinterpret_cast<__half2*>(Ch + (size_t)m0 * N + n0) =
                    __floats2half2_rn(v00, v01);
                *reinterpret_cast<__half2*>(Ch + (size_t)(m0 + 8) * N + n0) =
                    __floats2half2_rn(v10, v11);
            } else {
                float* C0 = (float*)Cv + (size_t)m0 * N + n0;
                float* C1 = (float*)Cv + (size_t)(m0 + 8) * N + n0;
                if (EPI == 2) {
                    float2 o0 = *reinterpret_cast<float2*>(C0);
                    float2 o1 = *reinterpret_cast<float2*>(C1);
                    v00 += o0.x; v01 += o0.y;
                    v10 += o1.x; v11 += o1.y;
                }
                *reinterpret_cast<float2*>(C0) = make_float2(v00, v01);
                *reinterpret_cast<float2*>(C1) = make_float2(v10, v11);
            }
        }
    }
}

// ---------------- fp32 -> fp16 convert --------------------------------------
__global__ void f2h_k(const float* __restrict__ X, __half* __restrict__ Y, int n4) {
    int i = blockIdx.x * blockDim.x + threadIdx.x;
    if (i >= n4) return;
    float4 v = reinterpret_cast<const float4*>(X)[i];
    __half2* yp = reinterpret_cast<__half2*>(Y + (size_t)i * 4);
    yp[0] = __floats2half2_rn(v.x, v.y);
    yp[1] = __floats2half2_rn(v.z, v.w);
}

// ---------------- L2 normalize rows of 512 -> half --------------------------
__global__ void l2norm_h_k(const float* __restrict__ X, __half* __restrict__ Y) {
    __shared__ float red[4];
    int row = blockIdx.x;
    int tid = threadIdx.x;  // 128
    const float4* xp = reinterpret_cast<const float4*>(X + (size_t)row * CH);
    float4 v = xp[tid];
    float ss = v.x * v.x + v.y * v.y + v.z * v.z + v.w * v.w;
    #pragma unroll
    for (int o = 16; o > 0; o >>= 1) ss += __shfl_xor_sync(0xffffffffu, ss, o);
    if ((tid & 31) == 0) red[tid >> 5] = ss;
    __syncthreads();
    float rn = rsqrtf(red[0] + red[1] + red[2] + red[3]);
    __half2* yp = reinterpret_cast<__half2*>(Y + (size_t)row * CH + tid * 4);
    yp[0] = __floats2half2_rn(v.x * rn, v.y * rn);
    yp[1] = __floats2half2_rn(v.z * rn, v.w * rn);
}

// ---------------- exponential-decay scan (replaces FFT conv) ---------------
__global__ void decay_k(const float* __restrict__ QK, const float* __restrict__ alpha,
                        float* __restrict__ Q1, float* __restrict__ K1) {
    int g = blockIdx.x;      // 0..127
    int which = blockIdx.y;  // 0=q, 1=k
    int ch = threadIdx.x;    // 0..511
    int d = ch & 63;
    int nh = ch >> 6;
    float a = 1.f / (1.f + expf(-alpha[d]));
    float r = 1.f - a;
    float l2r = log2f(r);
    const float* x = QK + (size_t)g * (HTOK * 1024) + which * 512 + ch;
    float* y = (which ? K1 : Q1) + (size_t)g * (NHD * HTOK * HD) +
               (size_t)nh * (HTOK * HD) + d;
    float z = 0.f;
    for (int t = 0; t < HTOK; ++t) {
        z = fmaf(x[(size_t)t * 1024], exp2f((float)t * l2r), z);
        y[(size_t)t * 64] = a * exp2f((float)(HTOK - 1 - t) * l2r) * z;
    }
}

// ---------------- token attention: per head 192x64, online softmax ---------
__global__ void __launch_bounds__(192, 2) tok_attn_k(
    const float* __restrict__ Q1, const float* __restrict__ K1,
    const float* __restrict__ V, float* __restrict__ O) {
    extern __shared__ float sm[];
    float* Ks = sm;           // 12288
    float* Vs = sm + 12288;   // 12288
    int head = blockIdx.x;
    int g = head >> 3, nh = head & 7;
    int tid = threadIdx.x;
    const float4* Ksrc = reinterpret_cast<const float4*>(K1 + (size_t)head * 12288);
    float4* Kd = reinterpret_cast<float4*>(Ks);
    for (int i = tid; i < 3072; i += 192) Kd[i] = Ksrc[i];
    const float* Vbase = V + (size_t)g * HTOK * CH + nh * 64;
    for (int i = tid; i < 12288; i += 192) {
        int t = i >> 6, d = i & 63;
        Vs[i] = Vbase[(size_t)t * CH + d];
    }
    __syncthreads();
    int e = tid;
    float q[64];
    const float4* Qsrc = reinterpret_cast<const float4*>(Q1 + (size_t)head * 12288 + e * 64);
    #pragma unroll
    for (int j = 0; j < 16; j++) {
        float4 v4 = Qsrc[j];
        q[4*j] = v4.x; q[4*j+1] = v4.y; q[4*j+2] = v4.z; q[4*j+3] = v4.w;
    }
    float m = -1e30f, l = 0.f;
    float acc[64];
    #pragma unroll
    for (int j = 0; j < 64; j++) acc[j] = 0.f;
    for (int f = 0; f < HTOK; ++f) {
        const float4* kf = reinterpret_cast<const float4*>(Ks + f * 64);
        float s = 0.f;
        #pragma unroll
        for (int j = 0; j < 16; j++) {
            float4 kv = kf[j];
            s += q[4*j]*kv.x + q[4*j+1]*kv.y + q[4*j+2]*kv.z + q[4*j+3]*kv.w;
        }
        s *= 8.0f;  // * hd**0.5
        float mn = fmaxf(m, s);
        float corr = __expf(m - mn);
        float p = __expf(s - mn);
        l = l * corr + p;
        const float4* vf = reinterpret_cast<const float4*>(Vs + f * 64);
        #pragma unroll
        for (int j = 0; j < 16; j++) {
            float4 vv = vf[j];
            acc[4*j]   = acc[4*j]   * corr + p * vv.x;
            acc[4*j+1] = acc[4*j+1] * corr + p * vv.y;
            acc[4*j+2] = acc[4*j+2] * corr + p * vv.z;
            acc[4*j+3] = acc[4*j+3] * corr + p * vv.w;
        }
        m = mn;
    }
    float inv = 1.0f / l;
    float* Op = O + (size_t)head * 12288 + e * 64;
    #pragma unroll
    for (int d = 0; d < 64; d++) Op[d] = acc[d] * inv;
}

// ---------------- hidden attention: per head 64x64 over 192 ----------------
#define SPAD 65
__global__ void __launch_bounds__(256) hid_attn_k(
    const float* __restrict__ QK, const float* __restrict__ V,
    float* __restrict__ O) {
    extern __shared__ float sm[];
    float* qs = sm;            // 12288  (later reused for V)
    float* ks = sm + 12288;    // 12288
    float* ss = sm + 24576;    // 64*65
    int head = blockIdx.x;
    int g = head >> 3, nh = head & 7;
    int tid = threadIdx.x;
    const float* Qb = QK + (size_t)g * HTOK * 1024 + nh * 64;
    const float* Kb = Qb + 512;
    for (int i = tid; i < 12288; i += 256) {
        int a = i >> 6, e = i & 63;
        qs[i] = Qb[(size_t)a * 1024 + e];
        ks[i] = Kb[(size_t)a * 1024 + e];
    }
    __syncthreads();
    {
        int e = tid & 63;
        int f0 = (tid >> 6) << 4;  // 0,16,32,48
        float sacc[16];
        #pragma unroll
        for (int j = 0; j < 16; j++) sacc[j] = 0.f;
        for (int a = 0; a < HTOK; a++) {
            float qv = qs[a * 64 + e];
            const float* kr = ks + a * 64 + f0;
            #pragma unroll
            for (int j = 0; j < 16; j++) sacc[j] = fmaf(qv, kr[j], sacc[j]);
        }
        #pragma unroll
        for (int j = 0; j < 16; j++) ss[e * SPAD + f0 + j] = sacc[j] * 13.856406460551018f; // sqrt(192)
    }
    __syncthreads();
    if (tid < 64) {
        float* row = ss + tid * SPAD;
        float mx = row[0];
        #pragma unroll 8
        for (int f = 1; f < 64; f++) mx = fmaxf(mx, row[f]);
        float sum = 0.f;
        #pragma unroll 8
        for (int f = 0; f < 64; f++) { float p = __expf(row[f] - mx); row[f] = p; sum += p; }
        float inv = 1.0f / sum;
        #pragma unroll 8
        for (int f = 0; f < 64; f++) row[f] *= inv;
    }
    __syncthreads();
    const float* Vb = V + (size_t)g * HTOK * CH + nh * 64;
    for (int i = tid; i < 12288; i += 256) {
        int a = i >> 6, d = i & 63;
        qs[i] = Vb[(size_t)a * CH + d];
    }
    __syncthreads();
    float* Op = O + (size_t)head * 12288;
    for (int o = tid; o < 12288; o += 256) {
        int a = o >> 6, e = o & 63;
        const float* ar = ss + e * SPAD;
        const float* vr = qs + a * 64;
        float s = 0.f;
        #pragma unroll
        for (int f = 0; f < 64; f++) s = fmaf(ar[f], vr[f], s);
        Op[o] = s;
    }
}

// ---------------- BatchNorm (train-mode batch stats, per 512-channel) ------
__global__ void bn_partial_k(const float* __restrict__ X, const float* __restrict__ X2,
                             float* __restrict__ psum, float* __restrict__ psq) {
    int chunk = blockIdx.x;   // 192 chunks of 128 rows
    int ch = threadIdx.x;     // 512
    const float* p = X + (size_t)chunk * 128 * CH + ch;
    float s = 0.f, q = 0.f;
    if (X2) {
        const float* p2 = X2 + (size_t)chunk * 128 * CH + ch;
        for (int r = 0; r < 128; r++) {
            float v = p[(size_t)r * CH] + p2[(size_t)r * CH];
            s += v; q = fmaf(v, v, q);
        }
    } else {
        for (int r = 0; r < 128; r++) {
            float v = p[(size_t)r * CH];
            s += v; q = fmaf(v, v, q);
        }
    }
    psum[chunk * CH + ch] = s;
    psq[chunk * CH + ch] = q;
}

__global__ void bn_final_k(const float* __restrict__ psum, const float* __restrict__ psq,
                           const float* __restrict__ gamma, const float* __restrict__ beta,
                           float* __restrict__ scale, float* __restrict__ shift) {
    int ch = threadIdx.x;  // 512
    float s = 0.f, q = 0.f;
    for (int c = 0; c < 192; c++) { s += psum[c * CH + ch]; q += psq[c * CH + ch]; }
    float mu = s * (1.0f / NTOK);
    float var = q * (1.0f / NTOK) - mu * mu;
    float sc = gamma[ch] * rsqrtf(var + 1e-5f);
    scale[ch] = sc;
    shift[ch] = beta[ch] - mu * sc;
}

// apply BN and write HALF output
__global__ void bn_apply_h_k(__half* __restrict__ Y, const float* __restrict__ X,
                             const float* __restrict__ scale, const float* __restrict__ shift) {
    int i = blockIdx.x * blockDim.x + threadIdx.x;  // float4 index
    int ch4 = (i & 127) << 2;
    float4 x = reinterpret_cast<const float4*>(X)[i];
    x.x = fmaf(x.x, scale[ch4 + 0], shift[ch4 + 0]);
    x.y = fmaf(x.y, scale[ch4 + 1], shift[ch4 + 1]);
    x.z = fmaf(x.z, scale[ch4 + 2], shift[ch4 + 2]);
    x.w = fmaf(x.w, scale[ch4 + 3], shift[ch4 + 3]);
    __half2* yp = reinterpret_cast<__half2*>(Y + (size_t)i * 4);
    yp[0] = __floats2half2_rn(x.x, x.y);
    yp[1] = __floats2half2_rn(x.z, x.w);
}

// apply BN (fp32 out, optional add of X2)
__global__ void bn_apply_k(float* __restrict__ Y, const float* __restrict__ X,
                           const float* __restrict__ X2,
                           const float* __restrict__ scale, const float* __restrict__ shift) {
    int i = blockIdx.x * blockDim.x + threadIdx.x;  // float4 index
    int ch4 = (i & 127) << 2;
    float4 x = reinterpret_cast<const float4*>(X)[i];
    if (X2) {
        float4 x2 = reinterpret_cast<const float4*>(X2)[i];
        x.x += x2.x; x.y += x2.y; x.z += x2.z; x.w += x2.w;
    }
    x.x = fmaf(x.x, scale[ch4 + 0], shift[ch4 + 0]);
    x.y = fmaf(x.y, scale[ch4 + 1], shift[ch4 + 1]);
    x.z = fmaf(x.z, scale[ch4 + 2], shift[ch4 + 2]);
    x.w = fmaf(x.w, scale[ch4 + 3], shift[ch4 + 3]);
    reinterpret_cast<float4*>(Y)[i] = x;
}

// ---------------- driver ----------------------------------------------------
extern "C" void kernel_launch(void* const* d_in, const int* in_sizes, int n_in,
                              void* d_out, int out_size) {
    const float* src    = (const float*)d_in[0];
    const float* qk_w   = (const float*)d_in[1];
    const float* qk_b   = (const float*)d_in[2];
    const float* v_w    = (const float*)d_in[3];
    const float* v_b    = (const float*)d_in[4];
    const float* alpha  = (const float*)d_in[5];
    const float* g_pre1 = (const float*)d_in[6];
    const float* b_pre1 = (const float*)d_in[7];
    const float* g_pre2 = (const float*)d_in[8];
    const float* b_pre2 = (const float*)d_in[9];
    const float* f1w1   = (const float*)d_in[10];
    const float* f1b1   = (const float*)d_in[11];
    const float* f1w2   = (const float*)d_in[12];
    const float* f1b2   = (const float*)d_in[13];
    const float* f2w1   = (const float*)d_in[14];
    const float* f2b1   = (const float*)d_in[15];
    const float* f2w2   = (const float*)d_in[16];
    const float* f2b2   = (const float*)d_in[17];
    const float* g_attn = (const float*)d_in[18];
    const float* b_attn = (const float*)d_in[19];
    float* out = (float*)d_out;

    float *QK, *Vb, *Q1, *K1, *OT, *OH, *ACC, *PS, *PQ, *SC, *SH;
    __half *S1h, *SRCh, *OTh, *OHh, *HBh, *WQK, *WV, *W11, *W12, *W21, *W22;
    cudaGetSymbolAddress((void**)&QK,  g_qkbuf);
    cudaGetSymbolAddress((void**)&Vb,  g_vbuf);
    cudaGetSymbolAddress((void**)&Q1,  g_q1);
    cudaGetSymbolAddress((void**)&K1,  g_k1);
    cudaGetSymbolAddress((void**)&OT,  g_ot);
    cudaGetSymbolAddress((void**)&OH,  g_oh);
    cudaGetSymbolAddress((void**)&ACC, g_accb);
    cudaGetSymbolAddress((void**)&PS,  g_ps);
    cudaGetSymbolAddress((void**)&PQ,  g_pq);
    cudaGetSymbolAddress((void**)&SC,  g_scv);
    cudaGetSymbolAddress((void**)&SH,  g_shv);
    cudaGetSymbolAddress((void**)&S1h,  g_s1h);
    cudaGetSymbolAddress((void**)&SRCh, g_srch);
    cudaGetSymbolAddress((void**)&OTh,  g_oth);
    cudaGetSymbolAddress((void**)&OHh,  g_ohh);
    cudaGetSymbolAddress((void**)&HBh,  g_hbh);
    cudaGetSymbolAddress((void**)&WQK,  g_wqk);
    cudaGetSymbolAddress((void**)&WV,   g_wv);
    cudaGetSymbolAddress((void**)&W11,  g_w11);
    cudaGetSymbolAddress((void**)&W12,  g_w12);
    cudaGetSymbolAddress((void**)&W21,  g_w21);
    cudaGetSymbolAddress((void**)&W22,  g_w22);

    const int GSM = 3 * HSTG_BYTES;  // 110592 B
    cudaFuncSetAttribute(hgemm_k<0>, cudaFuncAttributeMaxDynamicSharedMemorySize, GSM);
    cudaFuncSetAttribute(hgemm_k<1>, cudaFuncAttributeMaxDynamicSharedMemorySize, GSM);
    cudaFuncSetAttribute(hgemm_k<2>, cudaFuncAttributeMaxDynamicSharedMemorySize, GSM);
    cudaFuncSetAttribute(tok_attn_k, cudaFuncAttributeMaxDynamicSharedMemorySize, 98304);
    cudaFuncSetAttribute(hid_attn_k, cudaFuncAttributeMaxDynamicSharedMemorySize, (24576 + 64 * SPAD) * 4);

    // 0. convert weights + src to half
    f2h_k<<<512, 256>>>(qk_w, WQK, 1024 * 512 / 4);
    f2h_k<<<256, 256>>>(v_w, WV, 512 * 512 / 4);
    f2h_k<<<1024, 256>>>(f1w1, W11, 2048 * 512 / 4);
    f2h_k<<<1024, 256>>>(f1w2, W12, 512 * 2048 / 4);
    f2h_k<<<1024, 256>>>(f2w1, W21, 2048 * 512 / 4);
    f2h_k<<<1024, 256>>>(f2w2, W22, 512 * 2048 / 4);
    f2h_k<<<NELEM / 4 / 256, 256>>>(src, SRCh, NELEM / 4);
    // 1. normalize src -> half
    l2norm_h_k<<<NTOK, 128>>>(src, S1h);
    // 2. projections (fp16 tensor cores, fp32 accumulate)
    hgemm_k<0><<<192 * 8, 256, GSM>>>(S1h, WQK, qk_b, QK, 1024, 512, 8);
    hgemm_k<0><<<192 * 4, 256, GSM>>>(SRCh, WV, v_b, Vb, 512, 512, 4);
    // 3. decay scan -> q1, k1 (head-major)
    decay_k<<<dim3(G, 2), 512>>>(QK, alpha, Q1, K1);
    // 4. attentions
    tok_attn_k<<<1024, 192, 98304>>>(Q1, K1, Vb, OT);
    hid_attn_k<<<1024, 256, (24576 + 64 * SPAD) * 4>>>(QK, Vb, OH);
    // 5. BN(out_tok) with pre2 -> o3 (half)
    bn_partial_k<<<192, 512>>>(OT, nullptr, PS, PQ);
    bn_final_k<<<1, 512>>>(PS, PQ, g_pre2, b_pre2, SC, SH);
    bn_apply_h_k<<<NELEM / 4 / 256, 256>>>(OTh, OT, SC, SH);
    // 6. FF1: ACC = gelu(o3 @ w1^T + b1) @ w2^T + b2
    hgemm_k<1><<<192 * 16, 256, GSM>>>(OTh, W11, f1b1, HBh, 2048, 512, 16);
    hgemm_k<0><<<192 * 4, 256, GSM>>>(HBh, W12, f1b2, ACC, 512, 2048, 4);
    // 7. BN(out_hid) with pre1 -> o2 (half)
    bn_partial_k<<<192, 512>>>(OH, nullptr, PS, PQ);
    bn_final_k<<<1, 512>>>(PS, PQ, g_pre1, b_pre1, SC, SH);
    bn_apply_h_k<<<NELEM / 4 / 256, 256>>>(OHh, OH, SC, SH);
    // 8. FF2: ACC += gelu(o2 @ w1^T + b1) @ w2^T + b2
    hgemm_k<1><<<192 * 16, 256, GSM>>>(OHh, W21, f2b1, HBh, 2048, 512, 16);
    hgemm_k<2><<<192 * 4, 256, GSM>>>(HBh, W22, f2b2, ACC, 512, 2048, 4);
    // 9. final BN(src + ACC) with g_attn/b_attn -> out
    bn_partial_k<<<192, 512>>>(src, ACC, PS, PQ);
    bn_final_k<<<1, 512>>>(PS, PQ, g_attn, b_attn, SC, SH);
    bn_apply_k<<<NELEM / 4 / 256, 256>>>(out, src, ACC, SC, SH);
}

// round 6
// speedup vs baseline: 6.1061x; 1.4514x over previous
#include <cuda_runtime.h>
#include <cuda_fp16.h>
#include <math.h>
#include <stdint.h>

#define G     128       // B*NV
#define HTOK  192
#define CH    512
#define NHD   8
#define HD    64
#define DFFC  2048
#define NTOK  24576     // G*HTOK
#define NELEM 12582912  // NTOK*CH

// ---------------- scratch (static device globals; allocation-free) ----------
__device__ float g_qkbuf[NTOK * 1024]; // qk projection (fp32)
__device__ float g_vbuf[NELEM];        // v projection (fp32)
__device__ float g_ot[NELEM];          // token-attn out
__device__ float g_oh[NELEM];          // hidden-attn out
__device__ float g_accb[NELEM];        // src2 accumulator
__device__ float g_ps[192 * 512];
__device__ float g_pq[192 * 512];
__device__ float g_scv[512];
__device__ float g_shv[512];
// fp16 buffers
__device__ __half g_q1h[NELEM];          // decayed q (half, head-major)
__device__ __half g_k1h[NELEM];          // decayed k
__device__ __half g_s1h[NELEM];          // normalized src
__device__ __half g_srch[NELEM];         // src
__device__ __half g_oth[NELEM];          // BN(o3)
__device__ __half g_ohh[NELEM];          // BN(o2)
__device__ __half g_hbh[NTOK * DFFC];    // FF hidden
__device__ __half g_wqk[1024 * 512];
__device__ __half g_wv[512 * 512];
__device__ __half g_w11[2048 * 512];
__device__ __half g_w12[512 * 2048];
__device__ __half g_w21[2048 * 512];
__device__ __half g_w22[512 * 2048];

__device__ __forceinline__ uint32_t smem_u32(const void* p) {
    uint32_t a;
    asm("{ .reg .u64 t; cvta.to.shared.u64 t, %1; cvt.u32.u64 %0, t; }"
        : "=r"(a) : "l"(p));
    return a;
}
__device__ __forceinline__ void mma_f16(float* c, const uint32_t* a, const uint32_t* b) {
    asm volatile(
        "mma.sync.aligned.m16n8k16.row.col.f32.f16.f16.f32 "
        "{%0,%1,%2,%3}, {%4,%5,%6,%7}, {%8,%9}, {%0,%1,%2,%3};"
        : "+f"(c[0]), "+f"(c[1]), "+f"(c[2]), "+f"(c[3])
        : "r"(a[0]), "r"(a[1]), "r"(a[2]), "r"(a[3]), "r"(b[0]), "r"(b[1]));
}
#define LDSM4(r, a)                                                            \
    asm volatile("ldmatrix.sync.aligned.m8n8.x4.shared.b16 {%0,%1,%2,%3}, [%4];" \
        : "=r"((r)[0]), "=r"((r)[1]), "=r"((r)[2]), "=r"((r)[3]) : "r"(a))
#define LDSM2(r, a)                                                            \
    asm volatile("ldmatrix.sync.aligned.m8n8.x2.shared.b16 {%0,%1}, [%2];"     \
        : "=r"((r)[0]), "=r"((r)[1]) : "r"(a))
#define LDSM4T(r, a)                                                           \
    asm volatile("ldmatrix.sync.aligned.m8n8.x4.trans.shared.b16 {%0,%1,%2,%3}, [%4];" \
        : "=r"((r)[0]), "=r"((r)[1]), "=r"((r)[2]), "=r"((r)[3]) : "r"(a))
#define LDSM2T(r, a)                                                           \
    asm volatile("ldmatrix.sync.aligned.m8n8.x2.trans.shared.b16 {%0,%1}, [%2];" \
        : "=r"((r)[0]), "=r"((r)[1]) : "r"(a))

// ============ fp16 mma GEMM, cp.async 3-stage: C = epi(A@B^T + bias) ========
#define RSB 144                       // smem row stride bytes (64 halves + pad)
#define HSTG_BYTES (2 * 128 * RSB)    // 36864 per stage

template <int EPI>
__global__ void __launch_bounds__(256, 2) hgemm_k(
    const __half* __restrict__ A, const __half* __restrict__ B,
    const float* __restrict__ bias, void* __restrict__ Cv,
    int N, int K, int gridN) {
    extern __shared__ char hsm[];
    const int tid = threadIdx.x;
    const int wid = tid >> 5, lane = tid & 31;
    const int wm = wid >> 2, wn = wid & 3;
    const int g = lane >> 2, tig = lane & 3;

    int bid = blockIdx.x;
    int per = 8 * gridN;
    int grp = bid / per, rem = bid - grp * per;
    const int bm = (grp * 8 + (rem & 7)) * 128;
    const int bn = (rem >> 3) * 128;

    const uint32_t sbase = smem_u32(hsm);
    const int CCH = K >> 6;

    const int c_row = tid >> 3;
    const int c_cq = tid & 7;
    #define CPYH(c, s) do {                                                     \
        int _kc = (c) << 6;                                                     \
        uint32_t _sa = sbase + (uint32_t)(s) * HSTG_BYTES;                      \
        _Pragma("unroll")                                                       \
        for (int _i = 0; _i < 4; _i++) {                                        \
            int _row = c_row + _i * 32;                                         \
            uint32_t _off = (uint32_t)_row * RSB + (uint32_t)c_cq * 16u;        \
            const __half* _ga = A + (size_t)(bm + _row) * K + _kc + c_cq * 8;   \
            asm volatile("cp.async.cg.shared.global [%0], [%1], 16;"            \
                         :: "r"(_sa + _off), "l"(_ga));                         \
            const __half* _gb = B + (size_t)(bn + _row) * K + _kc + c_cq * 8;   \
            asm volatile("cp.async.cg.shared.global [%0], [%1], 16;"            \
                         :: "r"(_sa + 18432u + _off), "l"(_gb));                \
        }                                                                       \
    } while (0)

    CPYH(0, 0);
    asm volatile("cp.async.commit_group;" ::: "memory");
    CPYH(1, 1);
    asm volatile("cp.async.commit_group;" ::: "memory");

    float acc[4][4][4];
    #pragma unroll
    for (int mt = 0; mt < 4; mt++)
        #pragma unroll
        for (int nt = 0; nt < 4; nt++)
            #pragma unroll
            for (int i = 0; i < 4; i++) acc[mt][nt][i] = 0.f;

    asm volatile("cp.async.wait_group 1;" ::: "memory");
    __syncthreads();

    const int lr = lane & 7, sel = lane >> 3;
    const uint32_t aoff =
        (uint32_t)(wm * 64 + (sel & 1) * 8 + lr) * RSB + (uint32_t)((sel >> 1) * 8) * 2;
    const uint32_t boff =
        (uint32_t)(wn * 32 + lr) * RSB + (uint32_t)((sel & 1) * 8) * 2;

    for (int c = 0; c < CCH; c++) {
        int rs = c % 3;
        if (c + 2 < CCH) {
            int ws = rs + 2; if (ws >= 3) ws -= 3;
            CPYH(c + 2, ws);
        }
        asm volatile("cp.async.commit_group;" ::: "memory");

        uint32_t sA = sbase + (uint32_t)rs * HSTG_BYTES;
        uint32_t sB = sA + 18432u;
        #pragma unroll
        for (int kt = 0; kt < 4; kt++) {
            uint32_t af[4][4], bf[4][2];
            #pragma unroll
            for (int mt = 0; mt < 4; mt++)
                LDSM4(af[mt], sA + aoff + (uint32_t)(mt * 16) * RSB + (uint32_t)kt * 32u);
            #pragma unroll
            for (int nt = 0; nt < 4; nt++)
                LDSM2(bf[nt], sB + boff + (uint32_t)(nt * 8) * RSB + (uint32_t)kt * 32u);
            #pragma unroll
            for (int mt = 0; mt < 4; mt++)
                #pragma unroll
                for (int nt = 0; nt < 4; nt++)
                    mma_f16(acc[mt][nt], af[mt], bf[nt]);
        }
        asm volatile("cp.async.wait_group 1;" ::: "memory");
        __syncthreads();
    }

    #pragma unroll
    for (int mt = 0; mt < 4; mt++) {
        int m0 = bm + wm * 64 + mt * 16 + g;
        #pragma unroll
        for (int nt = 0; nt < 4; nt++) {
            int n0 = bn + wn * 32 + nt * 8 + tig * 2;
            float b0 = bias[n0], b1 = bias[n0 + 1];
            float v00 = acc[mt][nt][0] + b0;
            float v01 = acc[mt][nt][1] + b1;
            float v10 = acc[mt][nt][2] + b0;
            float v11 = acc[mt][nt][3] + b1;
            if (EPI == 1) {
                v00 = 0.5f * v00 * (1.0f + erff(v00 * 0.70710678118654752f));
                v01 = 0.5f * v01 * (1.0f + erff(v01 * 0.70710678118654752f));
                v10 = 0.5f * v10 * (1.0f + erff(v10 * 0.70710678118654752f));
                v11 = 0.5f * v11 * (1.0f + erff(v11 * 0.70710678118654752f));
                __half* Ch = (__half*)Cv;
                *reinterpret_cast<__half2*>(Ch + (size_t)m0 * N + n0) =
                    __floats2half2_rn(v00, v01);
                *reinterpret_cast<__half2*>(Ch + (size_t)(m0 + 8) * N + n0) =
                    __floats2half2_rn(v10, v11);
            } else {
                float* C0 = (float*)Cv + (size_t)m0 * N + n0;
                float* C1 = (float*)Cv + (size_t)(m0 + 8) * N + n0;
                if (EPI == 2) {
                    float2 o0 = *reinterpret_cast<float2*>(C0);
                    float2 o1 = *reinterpret_cast<float2*>(C1);
                    v00 += o0.x; v01 += o0.y;
                    v10 += o1.x; v11 += o1.y;
                }
                *reinterpret_cast<float2*>(C0) = make_float2(v00, v01);
                *reinterpret_cast<float2*>(C1) = make_float2(v10, v11);
            }
        }
    }
}

// ---------------- fp32 -> fp16 convert --------------------------------------
__global__ void f2h_k(const float* __restrict__ X, __half* __restrict__ Y, int n4) {
    int i = blockIdx.x * blockDim.x + threadIdx.x;
    if (i >= n4) return;
    float4 v = reinterpret_cast<const float4*>(X)[i];
    __half2* yp = reinterpret_cast<__half2*>(Y + (size_t)i * 4);
    yp[0] = __floats2half2_rn(v.x, v.y);
    yp[1] = __floats2half2_rn(v.z, v.w);
}

// ---------------- L2 normalize rows of 512 -> half --------------------------
__global__ void l2norm_h_k(const float* __restrict__ X, __half* __restrict__ Y) {
    __shared__ float red[4];
    int row = blockIdx.x;
    int tid = threadIdx.x;  // 128
    const float4* xp = reinterpret_cast<const float4*>(X + (size_t)row * CH);
    float4 v = xp[tid];
    float ss = v.x * v.x + v.y * v.y + v.z * v.z + v.w * v.w;
    #pragma unroll
    for (int o = 16; o > 0; o >>= 1) ss += __shfl_xor_sync(0xffffffffu, ss, o);
    if ((tid & 31) == 0) red[tid >> 5] = ss;
    __syncthreads();
    float rn = rsqrtf(red[0] + red[1] + red[2] + red[3]);
    __half2* yp = reinterpret_cast<__half2*>(Y + (size_t)row * CH + tid * 4);
    yp[0] = __floats2half2_rn(v.x * rn, v.y * rn);
    yp[1] = __floats2half2_rn(v.z * rn, v.w * rn);
}

// ---------------- exponential-decay scan -> half (head-major) ---------------
__global__ void decay_k(const float* __restrict__ QK, const float* __restrict__ alpha,
                        __half* __restrict__ Q1, __half* __restrict__ K1) {
    int g = blockIdx.x;      // 0..127
    int which = blockIdx.y;  // 0=q, 1=k
    int ch = threadIdx.x;    // 0..511
    int d = ch & 63;
    int nh = ch >> 6;
    float a = 1.f / (1.f + expf(-alpha[d]));
    float r = 1.f - a;
    float l2r = log2f(r);
    const float* x = QK + (size_t)g * (HTOK * 1024) + which * 512 + ch;
    __half* y = (which ? K1 : Q1) + (size_t)g * (NHD * HTOK * HD) +
                (size_t)nh * (HTOK * HD) + d;
    float z = 0.f;
    for (int t = 0; t < HTOK; ++t) {
        z = fmaf(x[(size_t)t * 1024], exp2f((float)t * l2r), z);
        y[(size_t)t * 64] = __float2half_rn(a * exp2f((float)(HTOK - 1 - t) * l2r) * z);
    }
}

// ============ token attention, fp16 mma: per-head 192x192x64 ================
// smem: [0: Q1/V tile 27648][27648: K1 27648][55296: Sf 150528][205824: linv 768]
#define SRF 196    // Sf float stride (784B rows)
#define TOK_SMEM 206592

__global__ void __launch_bounds__(256, 1) tok_attn_mma_k(
    const __half* __restrict__ Q1, const __half* __restrict__ K1,
    const float* __restrict__ V, float* __restrict__ O) {
    extern __shared__ char smc[];
    const uint32_t sb = smem_u32(smc);
    const uint32_t sQ = sb, sK = sb + 27648u, sS = sb + 55296u;
    float* Sf = reinterpret_cast<float*>(smc + 55296);
    float* linv = reinterpret_cast<float*>(smc + 205824);
    const int head = blockIdx.x;
    const int g = head >> 3, nh = head & 7;
    const int tid = threadIdx.x, wid = tid >> 5, lane = tid & 31;
    const int wm = wid >> 1, wn = wid & 1;        // 4m x 2n
    const int gq = lane >> 2, tg = lane & 3;
    const int lr = lane & 7, sel = lane >> 3;

    // load Q1, K1 tiles (half, rows of 64) via cp.async
    {
        const __half* Qg = Q1 + (size_t)head * 12288;
        const __half* Kg = K1 + (size_t)head * 12288;
        #pragma unroll
        for (int i = 0; i < 6; i++) {
            int idx = i * 256 + tid;          // 1536 16B-chunks per tile
            int row = idx >> 3, cq = idx & 7;
            uint32_t off = (uint32_t)row * RSB + (uint32_t)cq * 16u;
            asm volatile("cp.async.cg.shared.global [%0], [%1], 16;"
                         :: "r"(sQ + off), "l"(Qg + row * 64 + cq * 8));
            asm volatile("cp.async.cg.shared.global [%0], [%1], 16;"
                         :: "r"(sK + off), "l"(Kg + row * 64 + cq * 8));
        }
        asm volatile("cp.async.commit_group;" ::: "memory");
        asm volatile("cp.async.wait_group 0;" ::: "memory");
    }
    __syncthreads();

    // S = Q1 @ K1^T : warp tile 48x96
    {
        float acc[3][12][4];
        #pragma unroll
        for (int mt = 0; mt < 3; mt++)
            #pragma unroll
            for (int nt = 0; nt < 12; nt++)
                #pragma unroll
                for (int i = 0; i < 4; i++) acc[mt][nt][i] = 0.f;
        const int m0w = wm * 48, n0w = wn * 96;
        #pragma unroll
        for (int kt = 0; kt < 4; kt++) {
            uint32_t af[3][4], bf[12][2];
            #pragma unroll
            for (int mt = 0; mt < 3; mt++)
                LDSM4(af[mt], sQ + (uint32_t)(m0w + mt * 16 + (sel & 1) * 8 + lr) * RSB +
                              (uint32_t)(kt * 16 + (sel >> 1) * 8) * 2u);
            #pragma unroll
            for (int nt = 0; nt < 12; nt++)
                LDSM2(bf[nt], sK + (uint32_t)(n0w + nt * 8 + lr) * RSB +
                              (uint32_t)(kt * 16 + (sel & 1) * 8) * 2u);
            #pragma unroll
            for (int mt = 0; mt < 3; mt++)
                #pragma unroll
                for (int nt = 0; nt < 12; nt++)
                    mma_f16(acc[mt][nt], af[mt], bf[nt]);
        }
        // write S * 8 (sqrt(hd)) to Sf
        #pragma unroll
        for (int mt = 0; mt < 3; mt++) {
            int r0 = m0w + mt * 16 + gq;
            #pragma unroll
            for (int nt = 0; nt < 12; nt++) {
                int c0 = n0w + nt * 8 + tg * 2;
                Sf[r0 * SRF + c0]           = acc[mt][nt][0] * 8.0f;
                Sf[r0 * SRF + c0 + 1]       = acc[mt][nt][1] * 8.0f;
                Sf[(r0 + 8) * SRF + c0]     = acc[mt][nt][2] * 8.0f;
                Sf[(r0 + 8) * SRF + c0 + 1] = acc[mt][nt][3] * 8.0f;
            }
        }
    }
    __syncthreads();

    // load V (fp32 -> half) into Q1 region (Q1 is dead)
    {
        const float* Vg = V + (size_t)(g * 192) * 512 + nh * 64;
        #pragma unroll
        for (int i = 0; i < 12; i++) {
            int idx = i * 256 + tid;          // 3072 float4
            int row = idx >> 4, d4 = (idx & 15) * 4;
            float4 v = *reinterpret_cast<const float4*>(Vg + (size_t)row * 512 + d4);
            __half2* p = reinterpret_cast<__half2*>(smc + row * RSB + d4 * 2);
            p[0] = __floats2half2_rn(v.x, v.y);
            p[1] = __floats2half2_rn(v.z, v.w);
        }
    }
    // softmax over rows (tid < 192): max, exp->half P (in place), sum
    if (tid < 192) {
        float* row = Sf + tid * SRF;
        float mx = -1e30f;
        #pragma unroll 8
        for (int j = 0; j < 192; j += 4) {
            float4 v = *reinterpret_cast<const float4*>(row + j);
            mx = fmaxf(mx, fmaxf(fmaxf(v.x, v.y), fmaxf(v.z, v.w)));
        }
        float sum = 0.f;
        __half2* ph = reinterpret_cast<__half2*>(row);
        #pragma unroll 8
        for (int j = 0; j < 192; j += 4) {
            float4 v = *reinterpret_cast<const float4*>(row + j);
            float e0 = __expf(v.x - mx), e1 = __expf(v.y - mx);
            float e2 = __expf(v.z - mx), e3 = __expf(v.w - mx);
            sum += (e0 + e1) + (e2 + e3);
            ph[j >> 1] = __floats2half2_rn(e0, e1);
            ph[(j >> 1) + 1] = __floats2half2_rn(e2, e3);
        }
        linv[tid] = 1.0f / sum;
    }
    __syncthreads();

    // O = P @ V : warp tile 48x32 over k=192
    {
        float acc[3][4][4];
        #pragma unroll
        for (int mt = 0; mt < 3; mt++)
            #pragma unroll
            for (int nt = 0; nt < 4; nt++)
                #pragma unroll
                for (int i = 0; i < 4; i++) acc[mt][nt][i] = 0.f;
        const int m0 = wm * 48, n0 = wn * 32;
        #pragma unroll
        for (int kt = 0; kt < 12; kt++) {
            uint32_t af[3][4], bf[4][2];
            #pragma unroll
            for (int mt = 0; mt < 3; mt++)
                LDSM4(af[mt], sS + (uint32_t)(m0 + mt * 16 + (sel & 1) * 8 + lr) * 784u +
                              (uint32_t)(kt * 16 + (sel >> 1) * 8) * 2u);
            #pragma unroll
            for (int nt = 0; nt < 4; nt++)
                LDSM2T(bf[nt], sQ + (uint32_t)(kt * 16 + (sel & 1) * 8 + lr) * RSB +
                               (uint32_t)(n0 + nt * 8) * 2u);
            #pragma unroll
            for (int mt = 0; mt < 3; mt++)
                #pragma unroll
                for (int nt = 0; nt < 4; nt++)
                    mma_f16(acc[mt][nt], af[mt], bf[nt]);
        }
        float* Og = O + (size_t)head * 12288;
        #pragma unroll
        for (int mt = 0; mt < 3; mt++) {
            int r = m0 + mt * 16 + gq;
            float i0 = linv[r], i1 = linv[r + 8];
            #pragma unroll
            for (int nt = 0; nt < 4; nt++) {
                int c = n0 + nt * 8 + tg * 2;
                *reinterpret_cast<float2*>(Og + r * 64 + c) =
                    make_float2(acc[mt][nt][0] * i0, acc[mt][nt][1] * i0);
                *reinterpret_cast<float2*>(Og + (r + 8) * 64 + c) =
                    make_float2(acc[mt][nt][2] * i1, acc[mt][nt][3] * i1);
            }
        }
    }
}

// ============ hidden attention, fp16 mma: per-head 64x64 over 192 ===========
// smem: [0: Qh 27648][27648: Kh 27648][55296: Vh 27648][82944: S2f 17408]
//       [100352: P2h 9216][109568: linv2 256]  total 109824
#define HID_SMEM 109824

__global__ void __launch_bounds__(256, 2) hid_attn_mma_k(
    const float* __restrict__ QK, const float* __restrict__ V,
    float* __restrict__ O) {
    extern __shared__ char smc[];
    const uint32_t sb = smem_u32(smc);
    const uint32_t sQ = sb, sK = sb + 27648u, sV = sb + 55296u, sP = sb + 100352u;
    float* S2f = reinterpret_cast<float*>(smc + 82944);
    float* linv2 = reinterpret_cast<float*>(smc + 109568);
    const int head = blockIdx.x;
    const int g = head >> 3, nh = head & 7;
    const int tid = threadIdx.x, wid = tid >> 5, lane = tid & 31;
    const int gq = lane >> 2, tg = lane & 3;
    const int lr = lane & 7, sel = lane >> 3;

    // load + convert Q, K (from QK fp32) and V (from Vb fp32) into half tiles
    {
        const float* Qg = QK + (size_t)(g * 192) * 1024 + nh * 64;
        const float* Kg = Qg + 512;
        const float* Vg = V + (size_t)(g * 192) * 512 + nh * 64;
        #pragma unroll
        for (int i = 0; i < 12; i++) {
            int idx = i * 256 + tid;          // 3072 float4 per tile
            int row = idx >> 4, d4 = (idx & 15) * 4;
            uint32_t off = (uint32_t)row * RSB + (uint32_t)d4 * 2u;
            float4 q = *reinterpret_cast<const float4*>(Qg + (size_t)row * 1024 + d4);
            float4 k = *reinterpret_cast<const float4*>(Kg + (size_t)row * 1024 + d4);
            float4 v = *reinterpret_cast<const float4*>(Vg + (size_t)row * 512 + d4);
            __half2* pq = reinterpret_cast<__half2*>(smc + off);
            pq[0] = __floats2half2_rn(q.x, q.y); pq[1] = __floats2half2_rn(q.z, q.w);
            __half2* pk = reinterpret_cast<__half2*>(smc + 27648 + off);
            pk[0] = __floats2half2_rn(k.x, k.y); pk[1] = __floats2half2_rn(k.z, k.w);
            __half2* pv = reinterpret_cast<__half2*>(smc + 55296 + off);
            pv[0] = __floats2half2_rn(v.x, v.y); pv[1] = __floats2half2_rn(v.z, v.w);
        }
    }
    __syncthreads();

    // S2 = Q^T @ K (64x64 over a=192): warp grid 2m x 4n, warp tile 32x16
    {
        float acc[2][2][4];
        #pragma unroll
        for (int mt = 0; mt < 2; mt++)
            #pragma unroll
            for (int nt = 0; nt < 2; nt++)
                #pragma unroll
                for (int i = 0; i < 4; i++) acc[mt][nt][i] = 0.f;
        const int m0 = (wid >> 2) * 32, n0 = (wid & 3) * 16;
        #pragma unroll
        for (int kt = 0; kt < 12; kt++) {
            uint32_t af[2][4], bf[2][2];
            #pragma unroll
            for (int mt = 0; mt < 2; mt++)
                LDSM4T(af[mt], sQ + (uint32_t)(kt * 16 + (sel >> 1) * 8 + lr) * RSB +
                               (uint32_t)(m0 + mt * 16 + (sel & 1) * 8) * 2u);
            #pragma unroll
            for (int nt = 0; nt < 2; nt++)
                LDSM2T(bf[nt], sK + (uint32_t)(kt * 16 + (sel & 1) * 8 + lr) * RSB +
                               (uint32_t)(n0 + nt * 8) * 2u);
            #pragma unroll
            for (int mt = 0; mt < 2; mt++)
                #pragma unroll
                for (int nt = 0; nt < 2; nt++)
                    mma_f16(acc[mt][nt], af[mt], bf[nt]);
        }
        #pragma unroll
        for (int mt = 0; mt < 2; mt++) {
            int r0 = m0 + mt * 16 + gq;
            #pragma unroll
            for (int nt = 0; nt < 2; nt++) {
                int c0 = n0 + nt * 8 + tg * 2;
                S2f[r0 * 68 + c0]           = acc[mt][nt][0] * 13.856406460551018f;
                S2f[r0 * 68 + c0 + 1]       = acc[mt][nt][1] * 13.856406460551018f;
                S2f[(r0 + 8) * 68 + c0]     = acc[mt][nt][2] * 13.856406460551018f;
                S2f[(r0 + 8) * 68 + c0 + 1] = acc[mt][nt][3] * 13.856406460551018f;
            }
        }
    }
    __syncthreads();

    // softmax rows e (tid < 64) -> P2h half [e][72 halves]
    if (tid < 64) {
        float* row = S2f + tid * 68;
        float mx = -1e30f;
        #pragma unroll
        for (int j = 0; j < 64; j += 4) {
            float4 v = *reinterpret_cast<const float4*>(row + j);
            mx = fmaxf(mx, fmaxf(fmaxf(v.x, v.y), fmaxf(v.z, v.w)));
        }
        float sum = 0.f;
        __half2* ph = reinterpret_cast<__half2*>(smc + 100352 + tid * RSB);
        #pragma unroll
        for (int j = 0; j < 64; j += 4) {
            float4 v = *reinterpret_cast<const float4*>(row + j);
            float e0 = __expf(v.x - mx), e1 = __expf(v.y - mx);
            float e2 = __expf(v.z - mx), e3 = __expf(v.w - mx);
            sum += (e0 + e1) + (e2 + e3);
            ph[j >> 1] = __floats2half2_rn(e0, e1);
            ph[(j >> 1) + 1] = __floats2half2_rn(e2, e3);
        }
        linv2[tid] = 1.0f / sum;
    }
    __syncthreads();

    // O2 = V @ P2^T  (192x64 over f=64): warp grid 4m x 2n, warp tile 48x32
    {
        float acc[3][4][4];
        #pragma unroll
        for (int mt = 0; mt < 3; mt++)
            #pragma unroll
            for (int nt = 0; nt < 4; nt++)
                #pragma unroll
                for (int i = 0; i < 4; i++) acc[mt][nt][i] = 0.f;
        const int m0 = (wid >> 1) * 48, n0 = (wid & 1) * 32;
        #pragma unroll
        for (int kt = 0; kt < 4; kt++) {
            uint32_t af[3][4], bf[4][2];
            #pragma unroll
            for (int mt = 0; mt < 3; mt++)
                LDSM4(af[mt], sV + (uint32_t)(m0 + mt * 16 + (sel & 1) * 8 + lr) * RSB +
                              (uint32_t)(kt * 16 + (sel >> 1) * 8) * 2u);
            #pragma unroll
            for (int nt = 0; nt < 4; nt++)
                LDSM2(bf[nt], sP + (uint32_t)(n0 + nt * 8 + lr) * RSB +
                              (uint32_t)(kt * 16 + (sel & 1) * 8) * 2u);
            #pragma unroll
            for (int mt = 0; mt < 3; mt++)
                #pragma unroll
                for (int nt = 0; nt < 4; nt++)
                    mma_f16(acc[mt][nt], af[mt], bf[nt]);
        }
        float* Og = O + (size_t)head * 12288;
        #pragma unroll
        for (int mt = 0; mt < 3; mt++) {
            int r = m0 + mt * 16 + gq;
            #pragma unroll
            for (int nt = 0; nt < 4; nt++) {
                int c = n0 + nt * 8 + tg * 2;
                float i0 = linv2[c], i1 = linv2[c + 1];
                *reinterpret_cast<float2*>(Og + r * 64 + c) =
                    make_float2(acc[mt][nt][0] * i0, acc[mt][nt][1] * i1);
                *reinterpret_cast<float2*>(Og + (r + 8) * 64 + c) =
                    make_float2(acc[mt][nt][2] * i0, acc[mt][nt][3] * i1);
            }
        }
    }
}

// ---------------- BatchNorm (train-mode batch stats) ------------------------
__global__ void bn_partial_k(const float* __restrict__ X, const float* __restrict__ X2,
                             float* __restrict__ psum, float* __restrict__ psq) {
    int chunk = blockIdx.x;
    int ch = threadIdx.x;
    const float* p = X + (size_t)chunk * 128 * CH + ch;
    float s = 0.f, q = 0.f;
    if (X2) {
        const float* p2 = X2 + (size_t)chunk * 128 * CH + ch;
        for (int r = 0; r < 128; r++) {
            float v = p[(size_t)r * CH] + p2[(size_t)r * CH];
            s += v; q = fmaf(v, v, q);
        }
    } else {
        for (int r = 0; r < 128; r++) {
            float v = p[(size_t)r * CH];
            s += v; q = fmaf(v, v, q);
        }
    }
    psum[chunk * CH + ch] = s;
    psq[chunk * CH + ch] = q;
}

__global__ void bn_final_k(const float* __restrict__ psum, const float* __restrict__ psq,
                           const float* __restrict__ gamma, const float* __restrict__ beta,
                           float* __restrict__ scale, float* __restrict__ shift) {
    int ch = threadIdx.x;
    float s = 0.f, q = 0.f;
    for (int c = 0; c < 192; c++) { s += psum[c * CH + ch]; q += psq[c * CH + ch]; }
    float mu = s * (1.0f / NTOK);
    float var = q * (1.0f / NTOK) - mu * mu;
    float sc = gamma[ch] * rsqrtf(var + 1e-5f);
    scale[ch] = sc;
    shift[ch] = beta[ch] - mu * sc;
}

__global__ void bn_apply_h_k(__half* __restrict__ Y, const float* __restrict__ X,
                             const float* __restrict__ scale, const float* __restrict__ shift) {
    int i = blockIdx.x * blockDim.x + threadIdx.x;
    int ch4 = (i & 127) << 2;
    float4 x = reinterpret_cast<const float4*>(X)[i];
    x.x = fmaf(x.x, scale[ch4 + 0], shift[ch4 + 0]);
    x.y = fmaf(x.y, scale[ch4 + 1], shift[ch4 + 1]);
    x.z = fmaf(x.z, scale[ch4 + 2], shift[ch4 + 2]);
    x.w = fmaf(x.w, scale[ch4 + 3], shift[ch4 + 3]);
    __half2* yp = reinterpret_cast<__half2*>(Y + (size_t)i * 4);
    yp[0] = __floats2half2_rn(x.x, x.y);
    yp[1] = __floats2half2_rn(x.z, x.w);
}

__global__ void bn_apply_k(float* __restrict__ Y, const float* __restrict__ X,
                           const float* __restrict__ X2,
                           const float* __restrict__ scale, const float* __restrict__ shift) {
    int i = blockIdx.x * blockDim.x + threadIdx.x;
    int ch4 = (i & 127) << 2;
    float4 x = reinterpret_cast<const float4*>(X)[i];
    if (X2) {
        float4 x2 = reinterpret_cast<const float4*>(X2)[i];
        x.x += x2.x; x.y += x2.y; x.z += x2.z; x.w += x2.w;
    }
    x.x = fmaf(x.x, scale[ch4 + 0], shift[ch4 + 0]);
    x.y = fmaf(x.y, scale[ch4 + 1], shift[ch4 + 1]);
    x.z = fmaf(x.z, scale[ch4 + 2], shift[ch4 + 2]);
    x.w = fmaf(x.w, scale[ch4 + 3], shift[ch4 + 3]);
    reinterpret_cast<float4*>(Y)[i] = x;
}

// ---------------- driver ----------------------------------------------------
extern "C" void kernel_launch(void* const* d_in, const int* in_sizes, int n_in,
                              void* d_out, int out_size) {
    const float* src    = (const float*)d_in[0];
    const float* qk_w   = (const float*)d_in[1];
    const float* qk_b   = (const float*)d_in[2];
    const float* v_w    = (const float*)d_in[3];
    const float* v_b    = (const float*)d_in[4];
    const float* alpha  = (const float*)d_in[5];
    const float* g_pre1 = (const float*)d_in[6];
    const float* b_pre1 = (const float*)d_in[7];
    const float* g_pre2 = (const float*)d_in[8];
    const float* b_pre2 = (const float*)d_in[9];
    const float* f1w1   = (const float*)d_in[10];
    const float* f1b1   = (const float*)d_in[11];
    const float* f1w2   = (const float*)d_in[12];
    const float* f1b2   = (const float*)d_in[13];
    const float* f2w1   = (const float*)d_in[14];
    const float* f2b1   = (const float*)d_in[15];
    const float* f2w2   = (const float*)d_in[16];
    const float* f2b2   = (const float*)d_in[17];
    const float* g_attn = (const float*)d_in[18];
    const float* b_attn = (const float*)d_in[19];
    float* out = (float*)d_out;

    float *QK, *Vb, *OT, *OH, *ACC, *PS, *PQ, *SC, *SH;
    __half *Q1h, *K1h, *S1h, *SRCh, *OTh, *OHh, *HBh, *WQK, *WV, *W11, *W12, *W21, *W22;
    cudaGetSymbolAddress((void**)&QK,  g_qkbuf);
    cudaGetSymbolAddress((void**)&Vb,  g_vbuf);
    cudaGetSymbolAddress((void**)&OT,  g_ot);
    cudaGetSymbolAddress((void**)&OH,  g_oh);
    cudaGetSymbolAddress((void**)&ACC, g_accb);
    cudaGetSymbolAddress((void**)&PS,  g_ps);
    cudaGetSymbolAddress((void**)&PQ,  g_pq);
    cudaGetSymbolAddress((void**)&SC,  g_scv);
    cudaGetSymbolAddress((void**)&SH,  g_shv);
    cudaGetSymbolAddress((void**)&Q1h,  g_q1h);
    cudaGetSymbolAddress((void**)&K1h,  g_k1h);
    cudaGetSymbolAddress((void**)&S1h,  g_s1h);
    cudaGetSymbolAddress((void**)&SRCh, g_srch);
    cudaGetSymbolAddress((void**)&OTh,  g_oth);
    cudaGetSymbolAddress((void**)&OHh,  g_ohh);
    cudaGetSymbolAddress((void**)&HBh,  g_hbh);
    cudaGetSymbolAddress((void**)&WQK,  g_wqk);
    cudaGetSymbolAddress((void**)&WV,   g_wv);
    cudaGetSymbolAddress((void**)&W11,  g_w11);
    cudaGetSymbolAddress((void**)&W12,  g_w12);
    cudaGetSymbolAddress((void**)&W21,  g_w21);
    cudaGetSymbolAddress((void**)&W22,  g_w22);

    const int GSM = 3 * HSTG_BYTES;  // 110592
    cudaFuncSetAttribute(hgemm_k<0>, cudaFuncAttributeMaxDynamicSharedMemorySize, GSM);
    cudaFuncSetAttribute(hgemm_k<1>, cudaFuncAttributeMaxDynamicSharedMemorySize, GSM);
    cudaFuncSetAttribute(hgemm_k<2>, cudaFuncAttributeMaxDynamicSharedMemorySize, GSM);
    cudaFuncSetAttribute(tok_attn_mma_k, cudaFuncAttributeMaxDynamicSharedMemorySize, TOK_SMEM);
    cudaFuncSetAttribute(hid_attn_mma_k, cudaFuncAttributeMaxDynamicSharedMemorySize, HID_SMEM);

    // 0. convert weights + src to half
    f2h_k<<<512, 256>>>(qk_w, WQK, 1024 * 512 / 4);
    f2h_k<<<256, 256>>>(v_w, WV, 512 * 512 / 4);
    f2h_k<<<1024, 256>>>(f1w1, W11, 2048 * 512 / 4);
    f2h_k<<<1024, 256>>>(f1w2, W12, 512 * 2048 / 4);
    f2h_k<<<1024, 256>>>(f2w1, W21, 2048 * 512 / 4);
    f2h_k<<<1024, 256>>>(f2w2, W22, 512 * 2048 / 4);
    f2h_k<<<NELEM / 4 / 256, 256>>>(src, SRCh, NELEM / 4);
    // 1. normalize src -> half
    l2norm_h_k<<<NTOK, 128>>>(src, S1h);
    // 2. projections
    hgemm_k<0><<<192 * 8, 256, GSM>>>(S1h, WQK, qk_b, QK, 1024, 512, 8);
    hgemm_k<0><<<192 * 4, 256, GSM>>>(SRCh, WV, v_b, Vb, 512, 512, 4);
    // 3. decay scan -> q1, k1 (half, head-major)
    decay_k<<<dim3(G, 2), 512>>>(QK, alpha, Q1h, K1h);
    // 4. attentions (fp16 mma)
    tok_attn_mma_k<<<1024, 256, TOK_SMEM>>>(Q1h, K1h, Vb, OT);
    hid_attn_mma_k<<<1024, 256, HID_SMEM>>>(QK, Vb, OH);
    // 5. BN(out_tok) with pre2 -> o3 (half)
    bn_partial_k<<<192, 512>>>(OT, nullptr, PS, PQ);
    bn_final_k<<<1, 512>>>(PS, PQ, g_pre2, b_pre2, SC, SH);
    bn_apply_h_k<<<NELEM / 4 / 256, 256>>>(OTh, OT, SC, SH);
    // 6. FF1
    hgemm_k<1><<<192 * 16, 256, GSM>>>(OTh, W11, f1b1, HBh, 2048, 512, 16);
    hgemm_k<0><<<192 * 4, 256, GSM>>>(HBh, W12, f1b2, ACC, 512, 2048, 4);
    // 7. BN(out_hid) with pre1 -> o2 (half)
    bn_partial_k<<<192, 512>>>(OH, nullptr, PS, PQ);
    bn_final_k<<<1, 512>>>(PS, PQ, g_pre1, b_pre1, SC, SH);
    bn_apply_h_k<<<NELEM / 4 / 256, 256>>>(OHh, OH, SC, SH);
    // 8. FF2
    hgemm_k<1><<<192 * 16, 256, GSM>>>(OHh, W21, f2b1, HBh, 2048, 512, 16);
    hgemm_k<2><<<192 * 4, 256, GSM>>>(HBh, W22, f2b2, ACC, 512, 2048, 4);
    // 9. final BN(src + ACC) -> out
    bn_partial_k<<<192, 512>>>(src, ACC, PS, PQ);
    bn_final_k<<<1, 512>>>(PS, PQ, g_attn, b_attn, SC, SH);
    bn_apply_k<<<NELEM / 4 / 256, 256>>>(out, src, ACC, SC, SH);
}

// round 7
// speedup vs baseline: 6.4179x; 1.0511x over previous
#include <cuda_runtime.h>
#include <cuda_fp16.h>
#include <math.h>
#include <stdint.h>

#define G     128       // B*NV
#define HTOK  192
#define CH    512
#define NHD   8
#define HD    64
#define DFFC  2048
#define NTOK  24576     // G*HTOK
#define NELEM 12582912  // NTOK*CH

// ---------------- scratch (static device globals; allocation-free) ----------
__device__ float g_accb[NELEM];        // src2 accumulator (fp32)
__device__ float g_ps[192 * 512];
__device__ float g_pq[192 * 512];
__device__ float g_scv[512];
__device__ float g_shv[512];
// fp16 buffers
__device__ __half g_qkh[NTOK * 1024];    // qk projection (half)
__device__ __half g_vh[NELEM];           // v projection (half)
__device__ __half g_q1h[NELEM];          // decayed q (half, head-major)
__device__ __half g_k1h[NELEM];          // decayed k
__device__ __half g_s1h[NELEM];          // normalized src
__device__ __half g_srch[NELEM];         // src
__device__ __half g_otr[NELEM];          // token-attn out (raw, half)
__device__ __half g_ohr[NELEM];          // hidden-attn out (raw, half)
__device__ __half g_oth[NELEM];          // BN(o3) half
__device__ __half g_ohh[NELEM];          // BN(o2) half
__device__ __half g_hbh[NTOK * DFFC];    // FF hidden
__device__ __half g_wqk[1024 * 512];
__device__ __half g_wv[512 * 512];
__device__ __half g_w11[2048 * 512];
__device__ __half g_w12[512 * 2048];
__device__ __half g_w21[2048 * 512];
__device__ __half g_w22[512 * 2048];

__device__ __forceinline__ uint32_t smem_u32(const void* p) {
    uint32_t a;
    asm("{ .reg .u64 t; cvta.to.shared.u64 t, %1; cvt.u32.u64 %0, t; }"
        : "=r"(a) : "l"(p));
    return a;
}
__device__ __forceinline__ void mma_f16(float* c, const uint32_t* a, const uint32_t* b) {
    asm volatile(
        "mma.sync.aligned.m16n8k16.row.col.f32.f16.f16.f32 "
        "{%0,%1,%2,%3}, {%4,%5,%6,%7}, {%8,%9}, {%0,%1,%2,%3};"
        : "+f"(c[0]), "+f"(c[1]), "+f"(c[2]), "+f"(c[3])
        : "r"(a[0]), "r"(a[1]), "r"(a[2]), "r"(a[3]), "r"(b[0]), "r"(b[1]));
}
#define LDSM4(r, a)                                                            \
    asm volatile("ldmatrix.sync.aligned.m8n8.x4.shared.b16 {%0,%1,%2,%3}, [%4];" \
        : "=r"((r)[0]), "=r"((r)[1]), "=r"((r)[2]), "=r"((r)[3]) : "r"(a))
#define LDSM2(r, a)                                                            \
    asm volatile("ldmatrix.sync.aligned.m8n8.x2.shared.b16 {%0,%1}, [%2];"     \
        : "=r"((r)[0]), "=r"((r)[1]) : "r"(a))
#define LDSM4T(r, a)                                                           \
    asm volatile("ldmatrix.sync.aligned.m8n8.x4.trans.shared.b16 {%0,%1,%2,%3}, [%4];" \
        : "=r"((r)[0]), "=r"((r)[1]), "=r"((r)[2]), "=r"((r)[3]) : "r"(a))
#define LDSM2T(r, a)                                                           \
    asm volatile("ldmatrix.sync.aligned.m8n8.x2.trans.shared.b16 {%0,%1}, [%2];" \
        : "=r"((r)[0]), "=r"((r)[1]) : "r"(a))

// ============ fp16 mma GEMM, cp.async 3-stage: C = epi(A@B^T + bias) ========
#define RSB 144                       // smem row stride bytes (64 halves + pad)
#define HSTG_BYTES (2 * 128 * RSB)    // 36864 per stage

// EPI: 0 = store fp32, 1 = GELU -> half, 2 = accumulate fp32, 3 = store half
template <int EPI>
__global__ void __launch_bounds__(256, 2) hgemm_k(
    const __half* __restrict__ A, const __half* __restrict__ B,
    const float* __restrict__ bias, void* __restrict__ Cv,
    int N, int K, int gridN) {
    extern __shared__ char hsm[];
    const int tid = threadIdx.x;
    const int wid = tid >> 5, lane = tid & 31;
    const int wm = wid >> 2, wn = wid & 3;
    const int g = lane >> 2, tig = lane & 3;

    int bid = blockIdx.x;
    int per = 8 * gridN;
    int grp = bid / per, rem = bid - grp * per;
    const int bm = (grp * 8 + (rem & 7)) * 128;
    const int bn = (rem >> 3) * 128;

    const uint32_t sbase = smem_u32(hsm);
    const int CCH = K >> 6;

    const int c_row = tid >> 3;
    const int c_cq = tid & 7;
    #define CPYH(c, s) do {                                                     \
        int _kc = (c) << 6;                                                     \
        uint32_t _sa = sbase + (uint32_t)(s) * HSTG_BYTES;                      \
        _Pragma("unroll")                                                       \
        for (int _i = 0; _i < 4; _i++) {                                        \
            int _row = c_row + _i * 32;                                         \
            uint32_t _off = (uint32_t)_row * RSB + (uint32_t)c_cq * 16u;        \
            const __half* _ga = A + (size_t)(bm + _row) * K + _kc + c_cq * 8;   \
            asm volatile("cp.async.cg.shared.global [%0], [%1], 16;"            \
                         :: "r"(_sa + _off), "l"(_ga));                         \
            const __half* _gb = B + (size_t)(bn + _row) * K + _kc + c_cq * 8;   \
            asm volatile("cp.async.cg.shared.global [%0], [%1], 16;"            \
                         :: "r"(_sa + 18432u + _off), "l"(_gb));                \
        }                                                                       \
    } while (0)

    CPYH(0, 0);
    asm volatile("cp.async.commit_group;" ::: "memory");
    CPYH(1, 1);
    asm volatile("cp.async.commit_group;" ::: "memory");

    float acc[4][4][4];
    #pragma unroll
    for (int mt = 0; mt < 4; mt++)
        #pragma unroll
        for (int nt = 0; nt < 4; nt++)
            #pragma unroll
            for (int i = 0; i < 4; i++) acc[mt][nt][i] = 0.f;

    asm volatile("cp.async.wait_group 1;" ::: "memory");
    __syncthreads();

    const int lr = lane & 7, sel = lane >> 3;
    const uint32_t aoff =
        (uint32_t)(wm * 64 + (sel & 1) * 8 + lr) * RSB + (uint32_t)((sel >> 1) * 8) * 2;
    const uint32_t boff =
        (uint32_t)(wn * 32 + lr) * RSB + (uint32_t)((sel & 1) * 8) * 2;

    for (int c = 0; c < CCH; c++) {
        int rs = c % 3;
        if (c + 2 < CCH) {
            int ws = rs + 2; if (ws >= 3) ws -= 3;
            CPYH(c + 2, ws);
        }
        asm volatile("cp.async.commit_group;" ::: "memory");

        uint32_t sA = sbase + (uint32_t)rs * HSTG_BYTES;
        uint32_t sB = sA + 18432u;
        #pragma unroll
        for (int kt = 0; kt < 4; kt++) {
            uint32_t af[4][4], bf[4][2];
            #pragma unroll
            for (int mt = 0; mt < 4; mt++)
                LDSM4(af[mt], sA + aoff + (uint32_t)(mt * 16) * RSB + (uint32_t)kt * 32u);
            #pragma unroll
            for (int nt = 0; nt < 4; nt++)
                LDSM2(bf[nt], sB + boff + (uint32_t)(nt * 8) * RSB + (uint32_t)kt * 32u);
            #pragma unroll
            for (int mt = 0; mt < 4; mt++)
                #pragma unroll
                for (int nt = 0; nt < 4; nt++)
                    mma_f16(acc[mt][nt], af[mt], bf[nt]);
        }
        asm volatile("cp.async.wait_group 1;" ::: "memory");
        __syncthreads();
    }

    #pragma unroll
    for (int mt = 0; mt < 4; mt++) {
        int m0 = bm + wm * 64 + mt * 16 + g;
        #pragma unroll
        for (int nt = 0; nt < 4; nt++) {
            int n0 = bn + wn * 32 + nt * 8 + tig * 2;
            float b0 = bias[n0], b1 = bias[n0 + 1];
            float v00 = acc[mt][nt][0] + b0;
            float v01 = acc[mt][nt][1] + b1;
            float v10 = acc[mt][nt][2] + b0;
            float v11 = acc[mt][nt][3] + b1;
            if (EPI == 1 || EPI == 3) {
                if (EPI == 1) {
                    v00 = 0.5f * v00 * (1.0f + erff(v00 * 0.70710678118654752f));
                    v01 = 0.5f * v01 * (1.0f + erff(v01 * 0.70710678118654752f));
                    v10 = 0.5f * v10 * (1.0f + erff(v10 * 0.70710678118654752f));
                    v11 = 0.5f * v11 * (1.0f + erff(v11 * 0.70710678118654752f));
                }
                __half* Ch = (__half*)Cv;
                *reinterpret_cast<__half2*>(Ch + (size_t)m0 * N + n0) =
                    __floats2half2_rn(v00, v01);
                *reinterpret_cast<__half2*>(Ch + (size_t)(m0 + 8) * N + n0) =
                    __floats2half2_rn(v10, v11);
            } else {
                float* C0 = (float*)Cv + (size_t)m0 * N + n0;
                float* C1 = (float*)Cv + (size_t)(m0 + 8) * N + n0;
                if (EPI == 2) {
                    float2 o0 = *reinterpret_cast<float2*>(C0);
                    float2 o1 = *reinterpret_cast<float2*>(C1);
                    v00 += o0.x; v01 += o0.y;
                    v10 += o1.x; v11 += o1.y;
                }
                *reinterpret_cast<float2*>(C0) = make_float2(v00, v01);
                *reinterpret_cast<float2*>(C1) = make_float2(v10, v11);
            }
        }
    }
}

// ---------------- fp32 -> fp16 convert --------------------------------------
__global__ void f2h_k(const float* __restrict__ X, __half* __restrict__ Y, int n4) {
    int i = blockIdx.x * blockDim.x + threadIdx.x;
    if (i >= n4) return;
    float4 v = reinterpret_cast<const float4*>(X)[i];
    __half2* yp = reinterpret_cast<__half2*>(Y + (size_t)i * 4);
    yp[0] = __floats2half2_rn(v.x, v.y);
    yp[1] = __floats2half2_rn(v.z, v.w);
}

// ------------- fused: src -> srch (half) + l2-normalized src (half) ---------
__global__ void l2norm_src_k(const float* __restrict__ X,
                             __half* __restrict__ Yn, __half* __restrict__ Yr) {
    __shared__ float red[4];
    int row = blockIdx.x;
    int tid = threadIdx.x;  // 128
    const float4* xp = reinterpret_cast<const float4*>(X + (size_t)row * CH);
    float4 v = xp[tid];
    float ss = v.x * v.x + v.y * v.y + v.z * v.z + v.w * v.w;
    #pragma unroll
    for (int o = 16; o > 0; o >>= 1) ss += __shfl_xor_sync(0xffffffffu, ss, o);
    if ((tid & 31) == 0) red[tid >> 5] = ss;
    __syncthreads();
    float rn = rsqrtf(red[0] + red[1] + red[2] + red[3]);
    __half2* yr = reinterpret_cast<__half2*>(Yr + (size_t)row * CH + tid * 4);
    yr[0] = __floats2half2_rn(v.x, v.y);
    yr[1] = __floats2half2_rn(v.z, v.w);
    __half2* yn = reinterpret_cast<__half2*>(Yn + (size_t)row * CH + tid * 4);
    yn[0] = __floats2half2_rn(v.x * rn, v.y * rn);
    yn[1] = __floats2half2_rn(v.z * rn, v.w * rn);
}

// ---------------- exponential-decay scan (half in -> half out) --------------
__global__ void decay_k(const __half* __restrict__ QK, const float* __restrict__ alpha,
                        __half* __restrict__ Q1, __half* __restrict__ K1) {
    int g = blockIdx.x;      // 0..127
    int which = blockIdx.y;  // 0=q, 1=k
    int ch = threadIdx.x;    // 0..511
    int d = ch & 63;
    int nh = ch >> 6;
    float a = 1.f / (1.f + expf(-alpha[d]));
    float r = 1.f - a;
    float l2r = log2f(r);
    const __half* x = QK + (size_t)g * (HTOK * 1024) + which * 512 + ch;
    __half* y = (which ? K1 : Q1) + (size_t)g * (NHD * HTOK * HD) +
                (size_t)nh * (HTOK * HD) + d;
    float z = 0.f;
    for (int t = 0; t < HTOK; ++t) {
        z = fmaf(__half2float(x[(size_t)t * 1024]), exp2f((float)t * l2r), z);
        y[(size_t)t * 64] = __float2half_rn(a * exp2f((float)(HTOK - 1 - t) * l2r) * z);
    }
}

// ============ token attention, fp16 mma: per-head 192x192x64 ================
#define SRF 196    // Sf float stride (784B rows)
#define TOK_SMEM 206592

__global__ void __launch_bounds__(256, 1) tok_attn_mma_k(
    const __half* __restrict__ Q1, const __half* __restrict__ K1,
    const __half* __restrict__ V, __half* __restrict__ O) {
    extern __shared__ char smc[];
    const uint32_t sb = smem_u32(smc);
    const uint32_t sQ = sb, sK = sb + 27648u, sS = sb + 55296u;
    float* Sf = reinterpret_cast<float*>(smc + 55296);
    float* linv = reinterpret_cast<float*>(smc + 205824);
    const int head = blockIdx.x;
    const int g = head >> 3, nh = head & 7;
    const int tid = threadIdx.x, wid = tid >> 5, lane = tid & 31;
    const int wm = wid >> 1, wn = wid & 1;        // 4m x 2n
    const int gq = lane >> 2, tg = lane & 3;
    const int lr = lane & 7, sel = lane >> 3;

    {
        const __half* Qg = Q1 + (size_t)head * 12288;
        const __half* Kg = K1 + (size_t)head * 12288;
        #pragma unroll
        for (int i = 0; i < 6; i++) {
            int idx = i * 256 + tid;
            int row = idx >> 3, cq = idx & 7;
            uint32_t off = (uint32_t)row * RSB + (uint32_t)cq * 16u;
            asm volatile("cp.async.cg.shared.global [%0], [%1], 16;"
                         :: "r"(sQ + off), "l"(Qg + row * 64 + cq * 8));
            asm volatile("cp.async.cg.shared.global [%0], [%1], 16;"
                         :: "r"(sK + off), "l"(Kg + row * 64 + cq * 8));
        }
        asm volatile("cp.async.commit_group;" ::: "memory");
        asm volatile("cp.async.wait_group 0;" ::: "memory");
    }
    __syncthreads();

    // S = Q1 @ K1^T : warp tile 48x96
    {
        float acc[3][12][4];
        #pragma unroll
        for (int mt = 0; mt < 3; mt++)
            #pragma unroll
            for (int nt = 0; nt < 12; nt++)
                #pragma unroll
                for (int i = 0; i < 4; i++) acc[mt][nt][i] = 0.f;
        const int m0w = wm * 48, n0w = wn * 96;
        #pragma unroll
        for (int kt = 0; kt < 4; kt++) {
            uint32_t af[3][4], bf[12][2];
            #pragma unroll
            for (int mt = 0; mt < 3; mt++)
                LDSM4(af[mt], sQ + (uint32_t)(m0w + mt * 16 + (sel & 1) * 8 + lr) * RSB +
                              (uint32_t)(kt * 16 + (sel >> 1) * 8) * 2u);
            #pragma unroll
            for (int nt = 0; nt < 12; nt++)
                LDSM2(bf[nt], sK + (uint32_t)(n0w + nt * 8 + lr) * RSB +
                              (uint32_t)(kt * 16 + (sel & 1) * 8) * 2u);
            #pragma unroll
            for (int mt = 0; mt < 3; mt++)
                #pragma unroll
                for (int nt = 0; nt < 12; nt++)
                    mma_f16(acc[mt][nt], af[mt], bf[nt]);
        }
        #pragma unroll
        for (int mt = 0; mt < 3; mt++) {
            int r0 = m0w + mt * 16 + gq;
            #pragma unroll
            for (int nt = 0; nt < 12; nt++) {
                int c0 = n0w + nt * 8 + tg * 2;
                Sf[r0 * SRF + c0]           = acc[mt][nt][0] * 8.0f;
                Sf[r0 * SRF + c0 + 1]       = acc[mt][nt][1] * 8.0f;
                Sf[(r0 + 8) * SRF + c0]     = acc[mt][nt][2] * 8.0f;
                Sf[(r0 + 8) * SRF + c0 + 1] = acc[mt][nt][3] * 8.0f;
            }
        }
    }
    __syncthreads();

    // V load (half, direct cp.async) into Q1 region; overlaps with softmax
    {
        const __half* Vg = V + (size_t)(g * 192) * 512 + nh * 64;
        #pragma unroll
        for (int i = 0; i < 6; i++) {
            int idx = i * 256 + tid;
            int row = idx >> 3, cq = idx & 7;
            asm volatile("cp.async.cg.shared.global [%0], [%1], 16;"
                         :: "r"(sQ + (uint32_t)row * RSB + (uint32_t)cq * 16u),
                            "l"(Vg + (size_t)row * 512 + cq * 8));
        }
        asm volatile("cp.async.commit_group;" ::: "memory");
    }
    // softmax over rows (tid < 192)
    if (tid < 192) {
        float* row = Sf + tid * SRF;
        float mx = -1e30f;
        #pragma unroll 8
        for (int j = 0; j < 192; j += 4) {
            float4 v = *reinterpret_cast<const float4*>(row + j);
            mx = fmaxf(mx, fmaxf(fmaxf(v.x, v.y), fmaxf(v.z, v.w)));
        }
        float sum = 0.f;
        __half2* ph = reinterpret_cast<__half2*>(row);
        #pragma unroll 8
        for (int j = 0; j < 192; j += 4) {
            float4 v = *reinterpret_cast<const float4*>(row + j);
            float e0 = __expf(v.x - mx), e1 = __expf(v.y - mx);
            float e2 = __expf(v.z - mx), e3 = __expf(v.w - mx);
            sum += (e0 + e1) + (e2 + e3);
            ph[j >> 1] = __floats2half2_rn(e0, e1);
            ph[(j >> 1) + 1] = __floats2half2_rn(e2, e3);
        }
        linv[tid] = 1.0f / sum;
    }
    asm volatile("cp.async.wait_group 0;" ::: "memory");
    __syncthreads();

    // O = P @ V : warp tile 48x32 over k=192
    {
        float acc[3][4][4];
        #pragma unroll
        for (int mt = 0; mt < 3; mt++)
            #pragma unroll
            for (int nt = 0; nt < 4; nt++)
                #pragma unroll
                for (int i = 0; i < 4; i++) acc[mt][nt][i] = 0.f;
        const int m0 = wm * 48, n0 = wn * 32;
        #pragma unroll
        for (int kt = 0; kt < 12; kt++) {
            uint32_t af[3][4], bf[4][2];
            #pragma unroll
            for (int mt = 0; mt < 3; mt++)
                LDSM4(af[mt], sS + (uint32_t)(m0 + mt * 16 + (sel & 1) * 8 + lr) * 784u +
                              (uint32_t)(kt * 16 + (sel >> 1) * 8) * 2u);
            #pragma unroll
            for (int nt = 0; nt < 4; nt++)
                LDSM2T(bf[nt], sQ + (uint32_t)(kt * 16 + (sel & 1) * 8 + lr) * RSB +
                               (uint32_t)(n0 + nt * 8) * 2u);
            #pragma unroll
            for (int mt = 0; mt < 3; mt++)
                #pragma unroll
                for (int nt = 0; nt < 4; nt++)
                    mma_f16(acc[mt][nt], af[mt], bf[nt]);
        }
        __half* Og = O + (size_t)head * 12288;
        #pragma unroll
        for (int mt = 0; mt < 3; mt++) {
            int r = m0 + mt * 16 + gq;
            float i0 = linv[r], i1 = linv[r + 8];
            #pragma unroll
            for (int nt = 0; nt < 4; nt++) {
                int c = n0 + nt * 8 + tg * 2;
                *reinterpret_cast<__half2*>(Og + r * 64 + c) =
                    __floats2half2_rn(acc[mt][nt][0] * i0, acc[mt][nt][1] * i0);
                *reinterpret_cast<__half2*>(Og + (r + 8) * 64 + c) =
                    __floats2half2_rn(acc[mt][nt][2] * i1, acc[mt][nt][3] * i1);
            }
        }
    }
}

// ============ hidden attention, fp16 mma: per-head 64x64 over 192 ===========
#define HID_SMEM 109824

__global__ void __launch_bounds__(256, 2) hid_attn_mma_k(
    const __half* __restrict__ QK, const __half* __restrict__ V,
    __half* __restrict__ O) {
    extern __shared__ char smc[];
    const uint32_t sb = smem_u32(smc);
    const uint32_t sQ = sb, sK = sb + 27648u, sV = sb + 55296u, sP = sb + 100352u;
    float* S2f = reinterpret_cast<float*>(smc + 82944);
    float* linv2 = reinterpret_cast<float*>(smc + 109568);
    const int head = blockIdx.x;
    const int g = head >> 3, nh = head & 7;
    const int tid = threadIdx.x, wid = tid >> 5, lane = tid & 31;
    const int gq = lane >> 2, tg = lane & 3;
    const int lr = lane & 7, sel = lane >> 3;

    {
        const __half* Qg = QK + (size_t)(g * 192) * 1024 + nh * 64;
        const __half* Kg = Qg + 512;
        const __half* Vg = V + (size_t)(g * 192) * 512 + nh * 64;
        #pragma unroll
        for (int i = 0; i < 6; i++) {
            int idx = i * 256 + tid;
            int row = idx >> 3, cq = idx & 7;
            uint32_t off = (uint32_t)row * RSB + (uint32_t)cq * 16u;
            asm volatile("cp.async.cg.shared.global [%0], [%1], 16;"
                         :: "r"(sQ + off), "l"(Qg + (size_t)row * 1024 + cq * 8));
            asm volatile("cp.async.cg.shared.global [%0], [%1], 16;"
                         :: "r"(sK + off), "l"(Kg + (size_t)row * 1024 + cq * 8));
            asm volatile("cp.async.cg.shared.global [%0], [%1], 16;"
                         :: "r"(sV + off), "l"(Vg + (size_t)row * 512 + cq * 8));
        }
        asm volatile("cp.async.commit_group;" ::: "memory");
        asm volatile("cp.async.wait_group 0;" ::: "memory");
    }
    __syncthreads();

    // S2 = Q^T @ K (64x64 over a=192)
    {
        float acc[2][2][4];
        #pragma unroll
        for (int mt = 0; mt < 2; mt++)
            #pragma unroll
            for (int nt = 0; nt < 2; nt++)
                #pragma unroll
                for (int i = 0; i < 4; i++) acc[mt][nt][i] = 0.f;
        const int m0 = (wid >> 2) * 32, n0 = (wid & 3) * 16;
        #pragma unroll
        for (int kt = 0; kt < 12; kt++) {
            uint32_t af[2][4], bf[2][2];
            #pragma unroll
            for (int mt = 0; mt < 2; mt++)
                LDSM4T(af[mt], sQ + (uint32_t)(kt * 16 + (sel >> 1) * 8 + lr) * RSB +
                               (uint32_t)(m0 + mt * 16 + (sel & 1) * 8) * 2u);
            #pragma unroll
            for (int nt = 0; nt < 2; nt++)
                LDSM2T(bf[nt], sK + (uint32_t)(kt * 16 + (sel & 1) * 8 + lr) * RSB +
                               (uint32_t)(n0 + nt * 8) * 2u);
            #pragma unroll
            for (int mt = 0; mt < 2; mt++)
                #pragma unroll
                for (int nt = 0; nt < 2; nt++)
                    mma_f16(acc[mt][nt], af[mt], bf[nt]);
        }
        #pragma unroll
        for (int mt = 0; mt < 2; mt++) {
            int r0 = m0 + mt * 16 + gq;
            #pragma unroll
            for (int nt = 0; nt < 2; nt++) {
                int c0 = n0 + nt * 8 + tg * 2;
                S2f[r0 * 68 + c0]           = acc[mt][nt][0] * 13.856406460551018f;
                S2f[r0 * 68 + c0 + 1]       = acc[mt][nt][1] * 13.856406460551018f;
                S2f[(r0 + 8) * 68 + c0]     = acc[mt][nt][2] * 13.856406460551018f;
                S2f[(r0 + 8) * 68 + c0 + 1] = acc[mt][nt][3] * 13.856406460551018f;
            }
        }
    }
    __syncthreads();

    if (tid < 64) {
        float* row = S2f + tid * 68;
        float mx = -1e30f;
        #pragma unroll
        for (int j = 0; j < 64; j += 4) {
            float4 v = *reinterpret_cast<const float4*>(row + j);
            mx = fmaxf(mx, fmaxf(fmaxf(v.x, v.y), fmaxf(v.z, v.w)));
        }
        float sum = 0.f;
        __half2* ph = reinterpret_cast<__half2*>(smc + 100352 + tid * RSB);
        #pragma unroll
        for (int j = 0; j < 64; j += 4) {
            float4 v = *reinterpret_cast<const float4*>(row + j);
            float e0 = __expf(v.x - mx), e1 = __expf(v.y - mx);
            float e2 = __expf(v.z - mx), e3 = __expf(v.w - mx);
            sum += (e0 + e1) + (e2 + e3);
            ph[j >> 1] = __floats2half2_rn(e0, e1);
            ph[(j >> 1) + 1] = __floats2half2_rn(e2, e3);
        }
        linv2[tid] = 1.0f / sum;
    }
    __syncthreads();

    // O2 = V @ P2^T (192x64 over f=64)
    {
        float acc[3][4][4];
        #pragma unroll
        for (int mt = 0; mt < 3; mt++)
            #pragma unroll
            for (int nt = 0; nt < 4; nt++)
                #pragma unroll
                for (int i = 0; i < 4; i++) acc[mt][nt][i] = 0.f;
        const int m0 = (wid >> 1) * 48, n0 = (wid & 1) * 32;
        #pragma unroll
        for (int kt = 0; kt < 4; kt++) {
            uint32_t af[3][4], bf[4][2];
            #pragma unroll
            for (int mt = 0; mt < 3; mt++)
                LDSM4(af[mt], sV + (uint32_t)(m0 + mt * 16 + (sel & 1) * 8 + lr) * RSB +
                              (uint32_t)(kt * 16 + (sel >> 1) * 8) * 2u);
            #pragma unroll
            for (int nt = 0; nt < 4; nt++)
                LDSM2(bf[nt], sP + (uint32_t)(n0 + nt * 8 + lr) * RSB +
                              (uint32_t)(kt * 16 + (sel & 1) * 8) * 2u);
            #pragma unroll
            for (int mt = 0; mt < 3; mt++)
                #pragma unroll
                for (int nt = 0; nt < 4; nt++)
                    mma_f16(acc[mt][nt], af[mt], bf[nt]);
        }
        __half* Og = O + (size_t)head * 12288;
        #pragma unroll
        for (int mt = 0; mt < 3; mt++) {
            int r = m0 + mt * 16 + gq;
            #pragma unroll
            for (int nt = 0; nt < 4; nt++) {
                int c = n0 + nt * 8 + tg * 2;
                float i0 = linv2[c], i1 = linv2[c + 1];
                *reinterpret_cast<__half2*>(Og + r * 64 + c) =
                    __floats2half2_rn(acc[mt][nt][0] * i0, acc[mt][nt][1] * i1);
                *reinterpret_cast<__half2*>(Og + (r + 8) * 64 + c) =
                    __floats2half2_rn(acc[mt][nt][2] * i0, acc[mt][nt][3] * i1);
            }
        }
    }
}

// ---------------- BatchNorm (train-mode batch stats) ------------------------
__global__ void bn_partial_h_k(const __half* __restrict__ X,
                               float* __restrict__ psum, float* __restrict__ psq) {
    int chunk = blockIdx.x;
    int ch = threadIdx.x;
    const __half* p = X + (size_t)chunk * 128 * CH + ch;
    float s = 0.f, q = 0.f;
    for (int r = 0; r < 128; r++) {
        float v = __half2float(p[(size_t)r * CH]);
        s += v; q = fmaf(v, v, q);
    }
    psum[chunk * CH + ch] = s;
    psq[chunk * CH + ch] = q;
}

__global__ void bn_partial_k(const float* __restrict__ X, const float* __restrict__ X2,
                             float* __restrict__ psum, float* __restrict__ psq) {
    int chunk = blockIdx.x;
    int ch = threadIdx.x;
    const float* p = X + (size_t)chunk * 128 * CH + ch;
    const float* p2 = X2 + (size_t)chunk * 128 * CH + ch;
    float s = 0.f, q = 0.f;
    for (int r = 0; r < 128; r++) {
        float v = p[(size_t)r * CH] + p2[(size_t)r * CH];
        s += v; q = fmaf(v, v, q);
    }
    psum[chunk * CH + ch] = s;
    psq[chunk * CH + ch] = q;
}

__global__ void bn_final_k(const float* __restrict__ psum, const float* __restrict__ psq,
                           const float* __restrict__ gamma, const float* __restrict__ beta,
                           float* __restrict__ scale, float* __restrict__ shift) {
    int ch = threadIdx.x;
    float s = 0.f, q = 0.f;
    for (int c = 0; c < 192; c++) { s += psum[c * CH + ch]; q += psq[c * CH + ch]; }
    float mu = s * (1.0f / NTOK);
    float var = q * (1.0f / NTOK) - mu * mu;
    float sc = gamma[ch] * rsqrtf(var + 1e-5f);
    scale[ch] = sc;
    shift[ch] = beta[ch] - mu * sc;
}

// half in -> half out
__global__ void bn_apply_hh_k(__half* __restrict__ Y, const __half* __restrict__ X,
                              const float* __restrict__ scale, const float* __restrict__ shift) {
    int i = blockIdx.x * blockDim.x + threadIdx.x;
    int ch4 = (i & 127) << 2;
    const __half2* xp = reinterpret_cast<const __half2*>(X + (size_t)i * 4);
    float2 a = __half22float2(xp[0]);
    float2 b = __half22float2(xp[1]);
    a.x = fmaf(a.x, scale[ch4 + 0], shift[ch4 + 0]);
    a.y = fmaf(a.y, scale[ch4 + 1], shift[ch4 + 1]);
    b.x = fmaf(b.x, scale[ch4 + 2], shift[ch4 + 2]);
    b.y = fmaf(b.y, scale[ch4 + 3], shift[ch4 + 3]);
    __half2* yp = reinterpret_cast<__half2*>(Y + (size_t)i * 4);
    yp[0] = __floats2half2_rn(a.x, a.y);
    yp[1] = __floats2half2_rn(b.x, b.y);
}

__global__ void bn_apply_k(float* __restrict__ Y, const float* __restrict__ X,
                           const float* __restrict__ X2,
                           const float* __restrict__ scale, const float* __restrict__ shift) {
    int i = blockIdx.x * blockDim.x + threadIdx.x;
    int ch4 = (i & 127) << 2;
    float4 x = reinterpret_cast<const float4*>(X)[i];
    float4 x2 = reinterpret_cast<const float4*>(X2)[i];
    x.x += x2.x; x.y += x2.y; x.z += x2.z; x.w += x2.w;
    x.x = fmaf(x.x, scale[ch4 + 0], shift[ch4 + 0]);
    x.y = fmaf(x.y, scale[ch4 + 1], shift[ch4 + 1]);
    x.z = fmaf(x.z, scale[ch4 + 2], shift[ch4 + 2]);
    x.w = fmaf(x.w, scale[ch4 + 3], shift[ch4 + 3]);
    reinterpret_cast<float4*>(Y)[i] = x;
}

// ---------------- driver ----------------------------------------------------
extern "C" void kernel_launch(void* const* d_in, const int* in_sizes, int n_in,
                              void* d_out, int out_size) {
    const float* src    = (const float*)d_in[0];
    const float* qk_w   = (const float*)d_in[1];
    const float* qk_b   = (const float*)d_in[2];
    const float* v_w    = (const float*)d_in[3];
    const float* v_b    = (const float*)d_in[4];
    const float* alpha  = (const float*)d_in[5];
    const float* g_pre1 = (const float*)d_in[6];
    const float* b_pre1 = (const float*)d_in[7];
    const float* g_pre2 = (const float*)d_in[8];
    const float* b_pre2 = (const float*)d_in[9];
    const float* f1w1   = (const float*)d_in[10];
    const float* f1b1   = (const float*)d_in[11];
    const float* f1w2   = (const float*)d_in[12];
    const float* f1b2   = (const float*)d_in[13];
    const float* f2w1   = (const float*)d_in[14];
    const float* f2b1   = (const float*)d_in[15];
    const float* f2w2   = (const float*)d_in[16];
    const float* f2b2   = (const float*)d_in[17];
    const float* g_attn = (const float*)d_in[18];
    const float* b_attn = (const float*)d_in[19];
    float* out = (float*)d_out;

    float *ACC, *PS, *PQ, *SC, *SH;
    __half *QKh, *Vh, *Q1h, *K1h, *S1h, *SRCh, *OTr, *OHr, *OTh, *OHh, *HBh;
    __half *WQK, *WV, *W11, *W12, *W21, *W22;
    cudaGetSymbolAddress((void**)&ACC, g_accb);
    cudaGetSymbolAddress((void**)&PS,  g_ps);
    cudaGetSymbolAddress((void**)&PQ,  g_pq);
    cudaGetSymbolAddress((void**)&SC,  g_scv);
    cudaGetSymbolAddress((void**)&SH,  g_shv);
    cudaGetSymbolAddress((void**)&QKh,  g_qkh);
    cudaGetSymbolAddress((void**)&Vh,   g_vh);
    cudaGetSymbolAddress((void**)&Q1h,  g_q1h);
    cudaGetSymbolAddress((void**)&K1h,  g_k1h);
    cudaGetSymbolAddress((void**)&S1h,  g_s1h);
    cudaGetSymbolAddress((void**)&SRCh, g_srch);
    cudaGetSymbolAddress((void**)&OTr,  g_otr);
    cudaGetSymbolAddress((void**)&OHr,  g_ohr);
    cudaGetSymbolAddress((void**)&OTh,  g_oth);
    cudaGetSymbolAddress((void**)&OHh,  g_ohh);
    cudaGetSymbolAddress((void**)&HBh,  g_hbh);
    cudaGetSymbolAddress((void**)&WQK,  g_wqk);
    cudaGetSymbolAddress((void**)&WV,   g_wv);
    cudaGetSymbolAddress((void**)&W11,  g_w11);
    cudaGetSymbolAddress((void**)&W12,  g_w12);
    cudaGetSymbolAddress((void**)&W21,  g_w21);
    cudaGetSymbolAddress((void**)&W22,  g_w22);

    const int GSM = 3 * HSTG_BYTES;  // 110592
    cudaFuncSetAttribute(hgemm_k<0>, cudaFuncAttributeMaxDynamicSharedMemorySize, GSM);
    cudaFuncSetAttribute(hgemm_k<1>, cudaFuncAttributeMaxDynamicSharedMemorySize, GSM);
    cudaFuncSetAttribute(hgemm_k<2>, cudaFuncAttributeMaxDynamicSharedMemorySize, GSM);
    cudaFuncSetAttribute(hgemm_k<3>, cudaFuncAttributeMaxDynamicSharedMemorySize, GSM);
    cudaFuncSetAttribute(tok_attn_mma_k, cudaFuncAttributeMaxDynamicSharedMemorySize, TOK_SMEM);
    cudaFuncSetAttribute(hid_attn_mma_k, cudaFuncAttributeMaxDynamicSharedMemorySize, HID_SMEM);

    // launches 1-5 (so that launch #6 = QK hgemm gets profiled by ncu -s 5 -c 1)
    f2h_k<<<512, 256>>>(qk_w, WQK, 1024 * 512 / 4);
    f2h_k<<<256, 256>>>(v_w, WV, 512 * 512 / 4);
    f2h_k<<<1024, 256>>>(f1w1, W11, 2048 * 512 / 4);
    f2h_k<<<1024, 256>>>(f2w1, W21, 2048 * 512 / 4);
    l2norm_src_k<<<NTOK, 128>>>(src, S1h, SRCh);
    // 6: QK projection (profiled)
    hgemm_k<3><<<192 * 8, 256, GSM>>>(S1h, WQK, qk_b, QKh, 1024, 512, 8);
    hgemm_k<3><<<192 * 4, 256, GSM>>>(SRCh, WV, v_b, Vh, 512, 512, 4);
    f2h_k<<<1024, 256>>>(f1w2, W12, 512 * 2048 / 4);
    f2h_k<<<1024, 256>>>(f2w2, W22, 512 * 2048 / 4);
    // decay scan -> q1, k1 (half, head-major)
    decay_k<<<dim3(G, 2), 512>>>(QKh, alpha, Q1h, K1h);
    // attentions (fp16 mma, half I/O)
    tok_attn_mma_k<<<1024, 256, TOK_SMEM>>>(Q1h, K1h, Vh, OTr);
    hid_attn_mma_k<<<1024, 256, HID_SMEM>>>(QKh, Vh, OHr);
    // BN(out_tok) with pre2 -> o3 (half)
    bn_partial_h_k<<<192, 512>>>(OTr, PS, PQ);
    bn_final_k<<<1, 512>>>(PS, PQ, g_pre2, b_pre2, SC, SH);
    bn_apply_hh_k<<<NELEM / 4 / 256, 256>>>(OTh, OTr, SC, SH);
    // FF1
    hgemm_k<1><<<192 * 16, 256, GSM>>>(OTh, W11, f1b1, HBh, 2048, 512, 16);
    hgemm_k<0><<<192 * 4, 256, GSM>>>(HBh, W12, f1b2, ACC, 512, 2048, 4);
    // BN(out_hid) with pre1 -> o2 (half)
    bn_partial_h_k<<<192, 512>>>(OHr, PS, PQ);
    bn_final_k<<<1, 512>>>(PS, PQ, g_pre1, b_pre1, SC, SH);
    bn_apply_hh_k<<<NELEM / 4 / 256, 256>>>(OHh, OHr, SC, SH);
    // FF2
    hgemm_k<1><<<192 * 16, 256, GSM>>>(OHh, W21, f2b1, HBh, 2048, 512, 16);
    hgemm_k<2><<<192 * 4, 256, GSM>>>(HBh, W22, f2b2, ACC, 512, 2048, 4);
    // final BN(src + ACC) -> out
    bn_partial_k<<<192, 512>>>(src, ACC, PS, PQ);
    bn_final_k<<<1, 512>>>(PS, PQ, g_attn, b_attn, SC, SH);
    bn_apply_k<<<NELEM / 4 / 256, 256>>>(out, src, ACC, SC, SH);
}